// round 3
// baseline (speedup 1.0000x reference)
#include <cuda_runtime.h>

#define BB 4
#define NN 2048
#define FF 64
#define HH 4
#define LOG2E 1.4426950408889634f

// -------------------- device scratch (no allocations allowed) --------------------
__device__ float g_Wqkv[64 * 192];      // fused Wqc@Wqe, q-cols pre-scaled by 0.25*log2e
__device__ float g_bqkv[192];           // fused bqc@Wqe + bqe (q part scaled)
__device__ float g_Wo[64 * 64];         // fused Woc@Woe
__device__ float g_bo[64];              // fused boc@Woe + boe
__device__ float g_fr[2];               // {sigmoid*log2e, (1-sigmoid)*log2e}
__device__ float g_qkv[BB * NN * 192];  // [b][n][q(64) k(64) v(64)]
__device__ float g_ctx[BB * NN * 64];   // attention context

// -------------------- f32x2 helpers (Blackwell packed fp32) --------------------
__device__ __forceinline__ unsigned long long pack2(float x, float y) {
    unsigned long long r;
    asm("mov.b64 %0, {%1, %2};" : "=l"(r) : "f"(x), "f"(y));
    return r;
}
__device__ __forceinline__ void unpack2(unsigned long long v, float& x, float& y) {
    asm("mov.b64 {%0, %1}, %2;" : "=f"(x), "=f"(y) : "l"(v));
}
#define FMA2(d, a, b) asm("fma.rn.f32x2 %0, %1, %2, %0;" : "+l"(d) : "l"(a), "l"(b))
__device__ __forceinline__ float ex2f(float x) {
    float y;
    asm("ex2.approx.f32 %0, %1;" : "=f"(y) : "f"(x));
    return y;
}

// -------------------- kernel 1: fold the low-rank projections --------------------
__global__ void prep_kernel(const float* __restrict__ Wqc, const float* __restrict__ bqc,
                            const float* __restrict__ Wqe, const float* __restrict__ bqe,
                            const float* __restrict__ Woc, const float* __restrict__ boc,
                            const float* __restrict__ Woe, const float* __restrict__ boe,
                            const float* __restrict__ gf) {
    int gtid = blockIdx.x * 256 + threadIdx.x;
    int gstr = gridDim.x * 256;
    const float QSCALE = 0.25f * LOG2E;  // fold 1/sqrt(hd) and log2e into q
    for (int idx = gtid; idx < 64 * 192; idx += gstr) {
        int i = idx / 192, j = idx % 192;
        float s = 0.f;
#pragma unroll
        for (int c = 0; c < 24; c++) s += Wqc[i * 24 + c] * Wqe[c * 192 + j];
        if (j < 64) s *= QSCALE;
        g_Wqkv[idx] = s;
    }
    for (int j = gtid; j < 192; j += gstr) {
        float s = bqe[j];
#pragma unroll
        for (int c = 0; c < 24; c++) s += bqc[c] * Wqe[c * 192 + j];
        if (j < 64) s *= QSCALE;
        g_bqkv[j] = s;
    }
    for (int idx = gtid; idx < 64 * 64; idx += gstr) {
        int i = idx >> 6, j = idx & 63;
        float s = 0.f;
#pragma unroll
        for (int c = 0; c < 8; c++) s += Woc[i * 8 + c] * Woe[c * 64 + j];
        g_Wo[idx] = s;
    }
    for (int j = gtid; j < 64; j += gstr) {
        float s = boe[j];
#pragma unroll
        for (int c = 0; c < 8; c++) s += boc[c] * Woe[c * 64 + j];
        g_bo[j] = s;
    }
    if (gtid == 0) {
        float fr = 1.f / (1.f + expf(-gf[0]));
        g_fr[0] = fr * LOG2E;
        g_fr[1] = (1.f - fr) * LOG2E;
    }
}

// -------------------- kernel 2: fused QKV projection --------------------
__global__ __launch_bounds__(256) void qkv_kernel(const float* __restrict__ feats) {
    __shared__ float sf[32][64];
    __shared__ float4 sW4[64][48];  // 192 floats per row
    int tid = threadIdx.x;
    int row0 = blockIdx.x * 32;
    for (int idx = tid; idx < 64 * 48; idx += 256)
        sW4[idx / 48][idx % 48] = ((const float4*)g_Wqkv)[idx];
    for (int idx = tid; idx < 32 * 64; idx += 256)
        sf[idx >> 6][idx & 63] = feats[(size_t)row0 * 64 + idx];
    __syncthreads();
    int r = tid >> 3, cg = tid & 7;  // 32 rows x 8 col-groups (24 cols each)
    float4 acc[6];
#pragma unroll
    for (int w = 0; w < 6; w++) acc[w] = ((const float4*)g_bqkv)[cg * 6 + w];
#pragma unroll 8
    for (int c = 0; c < 64; c++) {
        float f = sf[r][c];
#pragma unroll
        for (int w = 0; w < 6; w++) {
            float4 wv = sW4[c][cg * 6 + w];
            acc[w].x += f * wv.x; acc[w].y += f * wv.y;
            acc[w].z += f * wv.z; acc[w].w += f * wv.w;
        }
    }
    float4* dst = (float4*)&g_qkv[(size_t)(row0 + r) * 192 + cg * 24];
#pragma unroll
    for (int w = 0; w < 6; w++) dst[w] = acc[w];
}

// -------------------- kernel 3: fused attention (the hot kernel) --------------------
// Grid: 256 CTAs (b x 32-row blocks). CTA: 256 threads = 8 warps.
// Warp w: head h = w&3, phase p = w>>2 (contiguous 16-m half per phase).
// Lane = row within the 32-row block. All k/v/bf2 shared reads are warp-uniform
// (pure broadcast). Scores are small -> no max subtraction needed.
// Software pipelined: prefetch tile t+1 into registers while computing tile t,
// double-buffered smem.
__global__ __launch_bounds__(256, 2) void attn_kernel(const float* __restrict__ learned,
                                                      const float* __restrict__ fixedg,
                                                      const float* __restrict__ bf1,
                                                      const float* __restrict__ bf2) {
    __shared__ float skv[2][32][128];    // k (0..63) | v (64..127) per m
    __shared__ float scomb[2][32][33];   // fused graph (pre-scaled by log2e)
    __shared__ float sbf2[2][4][32][8];  // bias factor 2, [h][mi][c]
    __shared__ float sred[4][32][17];    // phase-combine buffer {l, acc[16]}

    int tid = threadIdx.x;
    int lane = tid & 31;
    int w = tid >> 5;
    int h = w & 3, p = w >> 2;
    int bid = blockIdx.x;
    int b = bid >> 6;             // 64 row-blocks per batch
    int n0 = (bid & 63) << 5;     // 32 rows per CTA
    int n = n0 + lane;
    int h16 = h * 16;
    int mbase = p << 4;           // contiguous 16-m half

    // preload q (pre-scaled by 0.25*log2e) and bf1 row (scale log2e here)
    unsigned long long q2[8], f1p[4];
    {
        const ulonglong2* qp = (const ulonglong2*)(g_qkv + ((size_t)(b * NN + n)) * 192 + h16);
        ulonglong2 a0 = qp[0], a1 = qp[1], a2 = qp[2], a3 = qp[3];
        q2[0] = a0.x; q2[1] = a0.y; q2[2] = a1.x; q2[3] = a1.y;
        q2[4] = a2.x; q2[5] = a2.y; q2[6] = a3.x; q2[7] = a3.y;
        const float4* fp4 = (const float4*)(bf1 + ((size_t)h * NN + n) * 8);
        float4 fa = fp4[0], fb = fp4[1];
        f1p[0] = pack2(fa.x * LOG2E, fa.y * LOG2E);
        f1p[1] = pack2(fa.z * LOG2E, fa.w * LOG2E);
        f1p[2] = pack2(fb.x * LOG2E, fb.y * LOG2E);
        f1p[3] = pack2(fb.z * LOG2E, fb.w * LOG2E);
    }
    float fr2 = g_fr[0];
    float fr12 = g_fr[1];

    // per-thread cooperative-load decompositions (fixed across tiles)
    int kv_mi = tid >> 5, kv_j4 = tid & 31;          // kv fill
    int gr_r = tid >> 3, gr_c = tid & 7;             // graph fill
    int bf_h = tid >> 6, bf_c = (tid & 63) >> 3, bf_m = tid & 7;  // bf2 fill

    const float* kvp = g_qkv + ((size_t)(b * NN + kv_mi)) * 192 + 64 + kv_j4 * 4;
    const float* lp = learned + ((size_t)(b * NN + n0 + gr_r)) * NN + gr_c * 4;
    const float* fp = fixedg + ((size_t)(n0 + gr_r)) * NN + gr_c * 4;
    const float* bp = bf2 + ((size_t)(bf_h * 8 + bf_c)) * NN + bf_m * 4;

    unsigned long long acc[8];
#pragma unroll
    for (int j = 0; j < 8; j++) acc[j] = 0ULL;
    float l = 0.f;

    float4 rkv0, rkv1, rkv2, rkv3, rl4, rf4, rb4;
#define PREFETCH(M0)                                            \
    do {                                                        \
        const float* kq = kvp + (size_t)(M0) * 192;             \
        rkv0 = *(const float4*)(kq);                            \
        rkv1 = *(const float4*)(kq + 8 * 192);                  \
        rkv2 = *(const float4*)(kq + 16 * 192);                 \
        rkv3 = *(const float4*)(kq + 24 * 192);                 \
        rl4 = *(const float4*)(lp + (M0));                      \
        rf4 = *(const float4*)(fp + (M0));                      \
        rb4 = *(const float4*)(bp + (M0));                      \
    } while (0)

#define STORE_TILE(NB)                                          \
    do {                                                        \
        *(float4*)&skv[NB][kv_mi][kv_j4 * 4] = rkv0;            \
        *(float4*)&skv[NB][kv_mi + 8][kv_j4 * 4] = rkv1;        \
        *(float4*)&skv[NB][kv_mi + 16][kv_j4 * 4] = rkv2;       \
        *(float4*)&skv[NB][kv_mi + 24][kv_j4 * 4] = rkv3;       \
        scomb[NB][gr_r][gr_c * 4 + 0] = fr2 * rl4.x + fr12 * rf4.x; \
        scomb[NB][gr_r][gr_c * 4 + 1] = fr2 * rl4.y + fr12 * rf4.y; \
        scomb[NB][gr_r][gr_c * 4 + 2] = fr2 * rl4.z + fr12 * rf4.z; \
        scomb[NB][gr_r][gr_c * 4 + 3] = fr2 * rl4.w + fr12 * rf4.w; \
        sbf2[NB][bf_h][bf_m * 4 + 0][bf_c] = rb4.x;             \
        sbf2[NB][bf_h][bf_m * 4 + 1][bf_c] = rb4.y;             \
        sbf2[NB][bf_h][bf_m * 4 + 2][bf_c] = rb4.z;             \
        sbf2[NB][bf_h][bf_m * 4 + 3][bf_c] = rb4.w;             \
    } while (0)

    // preamble: fill buffer 0 with tile 0
    PREFETCH(0);
    STORE_TILE(0);
    __syncthreads();

    for (int t = 0; t < 64; t++) {
        int cb = t & 1;
        if (t < 63) PREFETCH((t + 1) * 32);   // overlaps with compute below

        // ---- inner loop: 16 m per warp (contiguous phase half) ----
#pragma unroll 4
        for (int i = 0; i < 16; i++) {
            int mi = mbase + i;
            unsigned long long s0 = pack2(scomb[cb][lane][mi], 0.f), s1 = 0ULL;
            const ulonglong2* kp = (const ulonglong2*)&skv[cb][mi][h16];
            ulonglong2 t0 = kp[0]; FMA2(s0, q2[0], t0.x); FMA2(s1, q2[1], t0.y);
            ulonglong2 t1 = kp[1]; FMA2(s0, q2[2], t1.x); FMA2(s1, q2[3], t1.y);
            ulonglong2 t2 = kp[2]; FMA2(s0, q2[4], t2.x); FMA2(s1, q2[5], t2.y);
            ulonglong2 t3 = kp[3]; FMA2(s0, q2[6], t3.x); FMA2(s1, q2[7], t3.y);
            const ulonglong2* bpp = (const ulonglong2*)&sbf2[cb][h][mi][0];
            ulonglong2 u0 = bpp[0]; FMA2(s0, f1p[0], u0.x); FMA2(s1, f1p[1], u0.y);
            ulonglong2 u1 = bpp[1]; FMA2(s0, f1p[2], u1.x); FMA2(s1, f1p[3], u1.y);
            float a0, a1, a2, a3;
            unpack2(s0, a0, a1); unpack2(s1, a2, a3);
            float e = ex2f((a0 + a2) + (a1 + a3));
            l += e;
            unsigned long long ee = pack2(e, e);
            const ulonglong2* vp = (const ulonglong2*)&skv[cb][mi][64 + h16];
            ulonglong2 v0 = vp[0]; FMA2(acc[0], ee, v0.x); FMA2(acc[1], ee, v0.y);
            ulonglong2 v1 = vp[1]; FMA2(acc[2], ee, v1.x); FMA2(acc[3], ee, v1.y);
            ulonglong2 v2 = vp[2]; FMA2(acc[4], ee, v2.x); FMA2(acc[5], ee, v2.y);
            ulonglong2 v3 = vp[3]; FMA2(acc[6], ee, v3.x); FMA2(acc[7], ee, v3.y);
        }
        __syncthreads();               // all warps done reading buf cb (and cb^1 from t-1)
        if (t < 63) {
            STORE_TILE(cb ^ 1);
            __syncthreads();           // publish buf cb^1 for tile t+1
        }
    }
#undef PREFETCH
#undef STORE_TILE

    // ---- combine the two m-phases, normalize, write context ----
    float av[16];
#pragma unroll
    for (int j = 0; j < 8; j++) unpack2(acc[j], av[2 * j], av[2 * j + 1]);
    __syncthreads();
    if (p == 1) {
        sred[h][lane][0] = l;
#pragma unroll
        for (int j = 0; j < 16; j++) sred[h][lane][1 + j] = av[j];
    }
    __syncthreads();
    if (p == 0) {
        l += sred[h][lane][0];
        float inv = 1.0f / l;
#pragma unroll
        for (int j = 0; j < 16; j++) av[j] = (av[j] + sred[h][lane][1 + j]) * inv;
        float* dst = g_ctx + ((size_t)(b * NN + n)) * 64 + h16;
        *(float4*)(dst + 0)  = make_float4(av[0], av[1], av[2], av[3]);
        *(float4*)(dst + 4)  = make_float4(av[4], av[5], av[6], av[7]);
        *(float4*)(dst + 8)  = make_float4(av[8], av[9], av[10], av[11]);
        *(float4*)(dst + 12) = make_float4(av[12], av[13], av[14], av[15]);
    }
}

// -------------------- kernel 4: output projection + residual + LayerNorm --------------------
__global__ __launch_bounds__(256) void epi_kernel(const float* __restrict__ feats,
                                                  const float* __restrict__ ln_g,
                                                  const float* __restrict__ ln_b,
                                                  float* __restrict__ out, int out_size) {
    __shared__ float4 sWo[64][16];
    __shared__ float sctx[16][64];
    int tid = threadIdx.x;
    int row0 = blockIdx.x * 16;
    for (int idx = tid; idx < 64 * 16; idx += 256)
        sWo[idx >> 4][idx & 15] = ((const float4*)g_Wo)[idx];
    for (int idx = tid; idx < 16 * 64; idx += 256)
        sctx[idx >> 6][idx & 63] = g_ctx[(size_t)row0 * 64 + idx];
    __syncthreads();
    int r = tid >> 4, cg = tid & 15;  // 16 rows x 16 col-groups (4 cols each)
    int row = row0 + r;
    float4 y = ((const float4*)g_bo)[cg];
#pragma unroll 8
    for (int c = 0; c < 64; c++) {
        float f = sctx[r][c];
        float4 wv = sWo[c][cg];
        y.x += f * wv.x; y.y += f * wv.y; y.z += f * wv.z; y.w += f * wv.w;
    }
    float4 res = *(const float4*)(feats + (size_t)row * 64 + cg * 4);
    y.x += res.x; y.y += res.y; y.z += res.z; y.w += res.w;
    float s1 = y.x + y.y + y.z + y.w;
    float s2 = y.x * y.x + y.y * y.y + y.z * y.z + y.w * y.w;
#pragma unroll
    for (int off = 8; off; off >>= 1) {
        s1 += __shfl_xor_sync(0xffffffffu, s1, off);
        s2 += __shfl_xor_sync(0xffffffffu, s2, off);
    }
    float mu = s1 * (1.f / 64.f);
    float var = s2 * (1.f / 64.f) - mu * mu;
    float rs = rsqrtf(var + 1e-5f);
    float4 g4 = *(const float4*)(ln_g + cg * 4);
    float4 b4 = *(const float4*)(ln_b + cg * 4);
    float4 o;
    o.x = (y.x - mu) * rs * g4.x + b4.x;
    o.y = (y.y - mu) * rs * g4.y + b4.y;
    o.z = (y.z - mu) * rs * g4.z + b4.z;
    o.w = (y.w - mu) * rs * g4.w + b4.w;
    *(float4*)(out + (size_t)row * 64 + cg * 4) = o;
    // reg_loss = 1e-5 * mean(|softmax|) == 1e-5 / N exactly (rows sum to 1, all >= 0)
    if (blockIdx.x == 0 && tid == 0) {
        for (int idx = BB * NN * FF; idx < out_size; idx++)
            out[idx] = 1e-5f / 2048.f;
    }
}

// -------------------- launch --------------------
extern "C" void kernel_launch(void* const* d_in, const int* in_sizes, int n_in,
                              void* d_out, int out_size) {
    const float* feats   = (const float*)d_in[0];
    const float* fixedg  = (const float*)d_in[1];
    const float* learned = (const float*)d_in[2];
    const float* Wqc = (const float*)d_in[3];
    const float* bqc = (const float*)d_in[4];
    const float* Wqe = (const float*)d_in[5];
    const float* bqe = (const float*)d_in[6];
    const float* Woc = (const float*)d_in[7];
    const float* boc = (const float*)d_in[8];
    const float* Woe = (const float*)d_in[9];
    const float* boe = (const float*)d_in[10];
    const float* bf1 = (const float*)d_in[11];
    const float* bf2 = (const float*)d_in[12];
    const float* gf  = (const float*)d_in[13];
    const float* lng = (const float*)d_in[14];
    const float* lnb = (const float*)d_in[15];
    float* out = (float*)d_out;

    prep_kernel<<<48, 256>>>(Wqc, bqc, Wqe, bqe, Woc, boc, Woe, boe, gf);
    qkv_kernel<<<BB * NN / 32, 256>>>(feats);
    attn_kernel<<<BB * NN / 32, 256>>>(learned, fixedg, bf1, bf2);
    epi_kernel<<<BB * NN / 16, 256>>>(feats, lng, lnb, out, out_size);
}

// round 4
// speedup vs baseline: 1.8953x; 1.8953x over previous
#include <cuda_runtime.h>
#include <cuda_fp16.h>
#include <cstdint>

#define BB 4
#define NN 2048
#define LOG2E 1.4426950408889634f

__device__ float g_Wqkv[64 * 192];
__device__ float g_bqkv[192];
__device__ float g_Wo[64 * 64];
__device__ float g_bo[64];
__device__ float g_fr[2];
__device__ float g_qkv[BB * NN * 192];
__device__ float g_kt[BB * 64 * NN];      // tf32 K^T [b][h*16+kd][n]
__device__ __half g_vt[BB * 64 * NN];     // f16 V^T [b][h*16+hd][n]
__device__ float g_bf2r[4 * 8 * NN];      // tf32 bf2 [h][c][n]
__device__ float g_ctx[BB * NN * 64];

__device__ __forceinline__ uint32_t f2tf32(float x) {
    uint32_t u; asm("cvt.rna.tf32.f32 %0, %1;" : "=r"(u) : "f"(x)); return u;
}
__device__ __forceinline__ float ex2f(float x) {
    float y; asm("ex2.approx.f32 %0, %1;" : "=f"(y) : "f"(x)); return y;
}
__device__ __forceinline__ uint32_t pack_h2(float lo, float hi) {
    uint32_t r; asm("cvt.rn.f16x2.f32 %0, %1, %2;" : "=r"(r) : "f"(hi), "f"(lo)); return r;
}
#define MMA_TF32(Cr, Ar, Br) asm volatile( \
    "mma.sync.aligned.m16n8k8.row.col.f32.tf32.tf32.f32 " \
    "{%0,%1,%2,%3}, {%4,%5,%6,%7}, {%8,%9}, {%0,%1,%2,%3};" \
    : "+f"(Cr[0]), "+f"(Cr[1]), "+f"(Cr[2]), "+f"(Cr[3]) \
    : "r"(Ar[0]), "r"(Ar[1]), "r"(Ar[2]), "r"(Ar[3]), "r"(Br[0]), "r"(Br[1]))
#define MMA_F16(Dr, Ar, Br) asm volatile( \
    "mma.sync.aligned.m16n8k16.row.col.f32.f16.f16.f32 " \
    "{%0,%1,%2,%3}, {%4,%5,%6,%7}, {%8,%9}, {%0,%1,%2,%3};" \
    : "+f"(Dr[0]), "+f"(Dr[1]), "+f"(Dr[2]), "+f"(Dr[3]) \
    : "r"(Ar[0]), "r"(Ar[1]), "r"(Ar[2]), "r"(Ar[3]), "r"(Br[0]), "r"(Br[1]))
#define CPA(dst, src) asm volatile("cp.async.cg.shared.global [%0], [%1], 16;" :: "r"(dst), "l"(src))
__device__ __forceinline__ float2 lds_v2(uint32_t a) {
    float2 v; asm("ld.shared.v2.f32 {%0,%1}, [%2];" : "=f"(v.x), "=f"(v.y) : "r"(a)); return v;
}
__device__ __forceinline__ uint32_t lds_b32(uint32_t a) {
    uint32_t v; asm("ld.shared.b32 %0, [%1];" : "=r"(v) : "r"(a)); return v;
}

// ---------- kernel 1: fold projections, round bf2 ----------
__global__ void prep_kernel(const float* __restrict__ Wqc, const float* __restrict__ bqc,
                            const float* __restrict__ Wqe, const float* __restrict__ bqe,
                            const float* __restrict__ Woc, const float* __restrict__ boc,
                            const float* __restrict__ Woe, const float* __restrict__ boe,
                            const float* __restrict__ gf, const float* __restrict__ bf2) {
    int gtid = blockIdx.x * 256 + threadIdx.x;
    int gstr = gridDim.x * 256;
    const float QS = 0.25f * LOG2E;
    for (int idx = gtid; idx < 64 * 192; idx += gstr) {
        int i = idx / 192, j = idx % 192;
        float s = 0.f;
#pragma unroll
        for (int c = 0; c < 24; c++) s += Wqc[i * 24 + c] * Wqe[c * 192 + j];
        if (j < 64) s *= QS;
        g_Wqkv[idx] = s;
    }
    for (int j = gtid; j < 192; j += gstr) {
        float s = bqe[j];
#pragma unroll
        for (int c = 0; c < 24; c++) s += bqc[c] * Wqe[c * 192 + j];
        if (j < 64) s *= QS;
        g_bqkv[j] = s;
    }
    for (int idx = gtid; idx < 64 * 64; idx += gstr) {
        int i = idx >> 6, j = idx & 63;
        float s = 0.f;
#pragma unroll
        for (int c = 0; c < 8; c++) s += Woc[i * 8 + c] * Woe[c * 64 + j];
        g_Wo[idx] = s;
    }
    for (int j = gtid; j < 64; j += gstr) {
        float s = boe[j];
#pragma unroll
        for (int c = 0; c < 8; c++) s += boc[c] * Woe[c * 64 + j];
        g_bo[j] = s;
    }
    for (int idx = gtid; idx < 4 * 8 * NN; idx += gstr)
        ((uint32_t*)g_bf2r)[idx] = f2tf32(bf2[idx]);
    if (gtid == 0) {
        float fr = 1.f / (1.f + expf(-gf[0]));
        g_fr[0] = fr * LOG2E;
        g_fr[1] = (1.f - fr) * LOG2E;
    }
}

// ---------- kernel 2: QKV projection ----------
__global__ __launch_bounds__(256) void qkv_kernel(const float* __restrict__ feats) {
    __shared__ float sf[32][64];
    __shared__ float4 sW4[64][48];
    int tid = threadIdx.x;
    int row0 = blockIdx.x * 32;
    for (int idx = tid; idx < 64 * 48; idx += 256)
        sW4[idx / 48][idx % 48] = ((const float4*)g_Wqkv)[idx];
    for (int idx = tid; idx < 32 * 64; idx += 256)
        sf[idx >> 6][idx & 63] = feats[(size_t)row0 * 64 + idx];
    __syncthreads();
    int r = tid >> 3, cg = tid & 7;
    float4 acc[6];
#pragma unroll
    for (int w = 0; w < 6; w++) acc[w] = ((const float4*)g_bqkv)[cg * 6 + w];
#pragma unroll 8
    for (int c = 0; c < 64; c++) {
        float f = sf[r][c];
#pragma unroll
        for (int w = 0; w < 6; w++) {
            float4 wv = sW4[c][cg * 6 + w];
            acc[w].x += f * wv.x; acc[w].y += f * wv.y;
            acc[w].z += f * wv.z; acc[w].w += f * wv.w;
        }
    }
    float4* dst = (float4*)&g_qkv[(size_t)(row0 + r) * 192 + cg * 24];
#pragma unroll
    for (int w = 0; w < 6; w++) dst[w] = acc[w];
}

// ---------- kernel 2b: transpose K (tf32) / V (f16) ----------
__global__ __launch_bounds__(256) void tr_kernel() {
    __shared__ float s[32][129];
    int tid = threadIdx.x;
    int n0g = blockIdx.x * 32;
#pragma unroll
    for (int k = 0; k < 4; k++) {
        int e = tid + k * 256;
        int r = e >> 5, c4 = e & 31;
        float4 v = *(const float4*)(g_qkv + (size_t)(n0g + r) * 192 + 64 + c4 * 4);
        s[r][c4 * 4 + 0] = v.x; s[r][c4 * 4 + 1] = v.y;
        s[r][c4 * 4 + 2] = v.z; s[r][c4 * 4 + 3] = v.w;
    }
    __syncthreads();
    int b = n0g >> 11, n0 = n0g & (NN - 1);
    int row = tid >> 2;
    int rc = (tid & 3) * 8;
    uint32_t* kdst = (uint32_t*)(g_kt + ((size_t)b * 64 + row) * NN + n0 + rc);
    __half* vdst = g_vt + ((size_t)b * 64 + row) * NN + n0 + rc;
#pragma unroll
    for (int i = 0; i < 8; i++) kdst[i] = f2tf32(s[rc + i][row]);
#pragma unroll
    for (int i = 0; i < 8; i++) vdst[i] = __float2half(s[rc + i][64 + row]);
}

// ---------- kernel 3: tensor-core fused attention ----------
#define BUF_K 0
#define BUF_V 15360
#define BUF_G 20480
#define BUFSZ 29696
#define SMEM_ATTN (2 * BUFSZ + 10240)

__global__ __launch_bounds__(256, 2) void attn_kernel(const float* __restrict__ learned,
                                                      const float* __restrict__ fixedg,
                                                      const float* __restrict__ bf1) {
    extern __shared__ char smem[];
    uint32_t sb = (uint32_t)__cvta_generic_to_shared(smem);
    int tid = threadIdx.x, lane = tid & 31, w = tid >> 5;
    int h = w & 3, p = w >> 2;
    int g4 = lane >> 2, t4 = lane & 3;
    int b = blockIdx.x >> 6, n0 = (blockIdx.x & 63) << 5;
    int mo = p << 4;

    // cp.async source/dst decompositions
    const float* kp[3]; uint32_t koff[3];
#pragma unroll
    for (int i = 0; i < 3; i++) {
        int idx = tid + 256 * i;
        int hk = idx >> 3, sub = idx & 7;
        int hh = hk / 24, kr = hk - hh * 24;
        const float* src = (kr < 16) ? (g_kt + ((size_t)(b * 4 + hh) * 16 + kr) * NN)
                                     : (g_bf2r + ((size_t)(hh * 8 + (kr - 16))) * NN);
        kp[i] = src + sub * 4;
        koff[i] = BUF_K + (hh * 24 + kr) * 160 + sub * 16;
    }
    const __half* vp; uint32_t voff;
    {
        int vrh = tid >> 2, sub = tid & 3;
        vp = g_vt + ((size_t)b * 64 + vrh) * NN + sub * 8;
        voff = BUF_V + vrh * 80 + sub * 16;
    }
    const float *lp, *fp; uint32_t loff, foff;
    {
        int r = tid >> 3, sub = tid & 7;
        lp = learned + ((size_t)(b * NN + n0 + r)) * NN + sub * 4;
        fp = fixedg + ((size_t)(n0 + r)) * NN + sub * 4;
        loff = BUF_G + r * 144 + sub * 16;
        foff = BUF_G + 4608 + r * 144 + sub * 16;
    }

    // persistent A fragments: [q*0.25*log2e | bf1*log2e] tf32
    uint32_t Aq[2][3][4];
#pragma unroll
    for (int ns = 0; ns < 2; ns++) {
        int r0 = n0 + ns * 16 + g4, r1 = r0 + 8;
#pragma unroll
        for (int ks = 0; ks < 3; ks++) {
            float v0, v1, v2, v3;
            if (ks < 2) {
                const float* q0 = g_qkv + ((size_t)(b * NN + r0)) * 192 + h * 16 + ks * 8;
                const float* q1 = g_qkv + ((size_t)(b * NN + r1)) * 192 + h * 16 + ks * 8;
                v0 = q0[t4]; v1 = q1[t4]; v2 = q0[t4 + 4]; v3 = q1[t4 + 4];
            } else {
                const float* f0 = bf1 + ((size_t)(h * NN + r0)) * 8;
                const float* f1 = bf1 + ((size_t)(h * NN + r1)) * 8;
                v0 = f0[t4] * LOG2E; v1 = f1[t4] * LOG2E;
                v2 = f0[t4 + 4] * LOG2E; v3 = f1[t4 + 4] * LOG2E;
            }
            Aq[ns][ks][0] = f2tf32(v0); Aq[ns][ks][1] = f2tf32(v1);
            Aq[ns][ks][2] = f2tf32(v2); Aq[ns][ks][3] = f2tf32(v3);
        }
    }
    float fr2 = g_fr[0], fr12 = g_fr[1];

    float D[2][2][4];
    float lacc[4] = {0.f, 0.f, 0.f, 0.f};
#pragma unroll
    for (int i = 0; i < 16; i++) ((float*)D)[i] = 0.f;

#define ISSUE(T)                                          \
    do {                                                  \
        int m0_ = (T) * 32;                               \
        uint32_t bb_ = sb + (((T) & 1) ? BUFSZ : 0);      \
        CPA(bb_ + koff[0], kp[0] + m0_);                  \
        CPA(bb_ + koff[1], kp[1] + m0_);                  \
        CPA(bb_ + koff[2], kp[2] + m0_);                  \
        CPA(bb_ + voff, vp + m0_);                        \
        CPA(bb_ + loff, lp + m0_);                        \
        CPA(bb_ + foff, fp + m0_);                        \
        asm volatile("cp.async.commit_group;");           \
    } while (0)

    ISSUE(0);
    for (int t = 0; t < 64; t++) {
        if (t < 63) { ISSUE(t + 1); asm volatile("cp.async.wait_group 1;"); }
        else        { asm volatile("cp.async.wait_group 0;"); }
        __syncthreads();
        uint32_t base = sb + ((t & 1) ? BUFSZ : 0);

        // B frags for K|bf2
        uint32_t bk[2][3][2];
        uint32_t kbase = base + BUF_K + h * 24 * 160 + (mo + g4) * 4;
#pragma unroll
        for (int ms = 0; ms < 2; ms++)
#pragma unroll
            for (int ks = 0; ks < 3; ks++) {
                uint32_t a0 = kbase + (ks * 8 + t4) * 160 + ms * 32;
                bk[ms][ks][0] = lds_b32(a0);
                bk[ms][ks][1] = lds_b32(a0 + 640);
            }
        // C init from fused graph
        float C[2][2][4];
        uint32_t gl = base + BUF_G + (mo + 2 * t4) * 4;
#pragma unroll
        for (int ns = 0; ns < 2; ns++)
#pragma unroll
            for (int ms = 0; ms < 2; ms++) {
                uint32_t a0 = gl + (ns * 16 + g4) * 144 + ms * 32;
                float2 l0 = lds_v2(a0), l1 = lds_v2(a0 + 8 * 144);
                float2 f0 = lds_v2(a0 + 4608), f1 = lds_v2(a0 + 4608 + 8 * 144);
                C[ns][ms][0] = fmaf(fr2, l0.x, fr12 * f0.x);
                C[ns][ms][1] = fmaf(fr2, l0.y, fr12 * f0.y);
                C[ns][ms][2] = fmaf(fr2, l1.x, fr12 * f1.x);
                C[ns][ms][3] = fmaf(fr2, l1.y, fr12 * f1.y);
            }
#pragma unroll
        for (int ns = 0; ns < 2; ns++)
#pragma unroll
            for (int ms = 0; ms < 2; ms++)
#pragma unroll
                for (int ks = 0; ks < 3; ks++) MMA_TF32(C[ns][ms], Aq[ns][ks], bk[ms][ks]);

        // p = 2^score, row sums
#pragma unroll
        for (int ns = 0; ns < 2; ns++)
#pragma unroll
            for (int ms = 0; ms < 2; ms++) {
                C[ns][ms][0] = ex2f(C[ns][ms][0]);
                C[ns][ms][1] = ex2f(C[ns][ms][1]);
                C[ns][ms][2] = ex2f(C[ns][ms][2]);
                C[ns][ms][3] = ex2f(C[ns][ms][3]);
                lacc[ns * 2 + 0] += C[ns][ms][0] + C[ns][ms][1];
                lacc[ns * 2 + 1] += C[ns][ms][2] + C[ns][ms][3];
            }
        // repack P as f16 A frags
        uint32_t pa[2][4];
#pragma unroll
        for (int ns = 0; ns < 2; ns++) {
            pa[ns][0] = pack_h2(C[ns][0][0], C[ns][0][1]);
            pa[ns][1] = pack_h2(C[ns][0][2], C[ns][0][3]);
            pa[ns][2] = pack_h2(C[ns][1][0], C[ns][1][1]);
            pa[ns][3] = pack_h2(C[ns][1][2], C[ns][1][3]);
        }
        // V B frags + PV mma
        uint32_t bv[2][2];
        uint32_t vb = base + BUF_V + (h * 16 + g4) * 80 + (mo + 2 * t4) * 2;
#pragma unroll
        for (int hs = 0; hs < 2; hs++) {
            bv[hs][0] = lds_b32(vb + hs * 640);
            bv[hs][1] = lds_b32(vb + hs * 640 + 16);
        }
#pragma unroll
        for (int ns = 0; ns < 2; ns++)
#pragma unroll
            for (int hs = 0; hs < 2; hs++) MMA_F16(D[ns][hs], pa[ns], bv[hs]);
        __syncthreads();
    }
#undef ISSUE

    // combine the two m-half warps
    float* sr = (float*)(smem + 2 * BUFSZ) + (h * 32 + lane) * 20;
    if (p == 1) {
#pragma unroll
        for (int i = 0; i < 16; i++) sr[i] = ((float*)D)[i];
#pragma unroll
        for (int i = 0; i < 4; i++) sr[16 + i] = lacc[i];
    }
    __syncthreads();
    if (p == 0) {
#pragma unroll
        for (int i = 0; i < 16; i++) ((float*)D)[i] += sr[i];
#pragma unroll
        for (int i = 0; i < 4; i++) lacc[i] += sr[16 + i];
        float inv[4];
#pragma unroll
        for (int i = 0; i < 4; i++) {
            float s = lacc[i];
            s += __shfl_xor_sync(0xffffffffu, s, 1);
            s += __shfl_xor_sync(0xffffffffu, s, 2);
            inv[i] = 1.0f / s;
        }
        float* dst = g_ctx + ((size_t)(b * NN + n0)) * 64 + h * 16;
#pragma unroll
        for (int ns = 0; ns < 2; ns++)
#pragma unroll
            for (int rh = 0; rh < 2; rh++) {
                int row = ns * 16 + g4 + rh * 8;
                float iv = inv[ns * 2 + rh];
#pragma unroll
                for (int hs = 0; hs < 2; hs++) {
                    float2 v = make_float2(D[ns][hs][rh * 2] * iv, D[ns][hs][rh * 2 + 1] * iv);
                    *(float2*)(dst + (size_t)row * 64 + hs * 8 + 2 * t4) = v;
                }
            }
    }
}

// ---------- kernel 4: output proj + residual + LayerNorm ----------
__global__ __launch_bounds__(256) void epi_kernel(const float* __restrict__ feats,
                                                  const float* __restrict__ ln_g,
                                                  const float* __restrict__ ln_b,
                                                  float* __restrict__ out, int out_size) {
    __shared__ float4 sWo[64][16];
    __shared__ float sctx[32][64];
    int tid = threadIdx.x;
    int row0 = blockIdx.x * 32;
    for (int idx = tid; idx < 64 * 16; idx += 256)
        sWo[idx >> 4][idx & 15] = ((const float4*)g_Wo)[idx];
    for (int idx = tid; idx < 512; idx += 256)
        ((float4*)sctx)[idx] = ((const float4*)(g_ctx + (size_t)row0 * 64))[idx];
    __syncthreads();
    int r = tid >> 3, cg = tid & 7;
    int row = row0 + r;
    float4 y0 = ((const float4*)g_bo)[cg * 2];
    float4 y1 = ((const float4*)g_bo)[cg * 2 + 1];
#pragma unroll 8
    for (int c = 0; c < 64; c++) {
        float f = sctx[r][c];
        float4 w0 = sWo[c][cg * 2], w1 = sWo[c][cg * 2 + 1];
        y0.x += f * w0.x; y0.y += f * w0.y; y0.z += f * w0.z; y0.w += f * w0.w;
        y1.x += f * w1.x; y1.y += f * w1.y; y1.z += f * w1.z; y1.w += f * w1.w;
    }
    float4 r0 = *(const float4*)(feats + (size_t)row * 64 + cg * 8);
    float4 r1 = *(const float4*)(feats + (size_t)row * 64 + cg * 8 + 4);
    y0.x += r0.x; y0.y += r0.y; y0.z += r0.z; y0.w += r0.w;
    y1.x += r1.x; y1.y += r1.y; y1.z += r1.z; y1.w += r1.w;
    float s1 = y0.x + y0.y + y0.z + y0.w + y1.x + y1.y + y1.z + y1.w;
    float s2 = y0.x * y0.x + y0.y * y0.y + y0.z * y0.z + y0.w * y0.w
             + y1.x * y1.x + y1.y * y1.y + y1.z * y1.z + y1.w * y1.w;
#pragma unroll
    for (int off = 4; off; off >>= 1) {
        s1 += __shfl_xor_sync(0xffffffffu, s1, off);
        s2 += __shfl_xor_sync(0xffffffffu, s2, off);
    }
    float mu = s1 * (1.f / 64.f);
    float var = s2 * (1.f / 64.f) - mu * mu;
    float rs = rsqrtf(var + 1e-5f);
    float4 g0 = *(const float4*)(ln_g + cg * 8), g1 = *(const float4*)(ln_g + cg * 8 + 4);
    float4 b0 = *(const float4*)(ln_b + cg * 8), b1 = *(const float4*)(ln_b + cg * 8 + 4);
    float4 o0, o1;
    o0.x = (y0.x - mu) * rs * g0.x + b0.x; o0.y = (y0.y - mu) * rs * g0.y + b0.y;
    o0.z = (y0.z - mu) * rs * g0.z + b0.z; o0.w = (y0.w - mu) * rs * g0.w + b0.w;
    o1.x = (y1.x - mu) * rs * g1.x + b1.x; o1.y = (y1.y - mu) * rs * g1.y + b1.y;
    o1.z = (y1.z - mu) * rs * g1.z + b1.z; o1.w = (y1.w - mu) * rs * g1.w + b1.w;
    *(float4*)(out + (size_t)row * 64 + cg * 8) = o0;
    *(float4*)(out + (size_t)row * 64 + cg * 8 + 4) = o1;
    if (blockIdx.x == 0 && tid == 0) {
        for (int idx = BB * NN * 64; idx < out_size; idx++)
            out[idx] = 1e-5f / 2048.f;
    }
}

// ---------- launch ----------
extern "C" void kernel_launch(void* const* d_in, const int* in_sizes, int n_in,
                              void* d_out, int out_size) {
    const float* feats   = (const float*)d_in[0];
    const float* fixedg  = (const float*)d_in[1];
    const float* learned = (const float*)d_in[2];
    const float* Wqc = (const float*)d_in[3];
    const float* bqc = (const float*)d_in[4];
    const float* Wqe = (const float*)d_in[5];
    const float* bqe = (const float*)d_in[6];
    const float* Woc = (const float*)d_in[7];
    const float* boc = (const float*)d_in[8];
    const float* Woe = (const float*)d_in[9];
    const float* boe = (const float*)d_in[10];
    const float* bf1 = (const float*)d_in[11];
    const float* bf2 = (const float*)d_in[12];
    const float* gf  = (const float*)d_in[13];
    const float* lng = (const float*)d_in[14];
    const float* lnb = (const float*)d_in[15];
    float* out = (float*)d_out;

    cudaFuncSetAttribute(attn_kernel, cudaFuncAttributeMaxDynamicSharedMemorySize, SMEM_ATTN);
    prep_kernel<<<48, 256>>>(Wqc, bqc, Wqe, bqe, Woc, boc, Woe, boe, gf, bf2);
    qkv_kernel<<<BB * NN / 32, 256>>>(feats);
    tr_kernel<<<BB * NN / 32, 256>>>();
    attn_kernel<<<BB * NN / 32, 256, SMEM_ATTN>>>(learned, fixedg, bf1);
    epi_kernel<<<BB * NN / 32, 256>>>(feats, lng, lnb, out, out_size);
}

// round 5
// speedup vs baseline: 1.9634x; 1.0359x over previous
#include <cuda_runtime.h>
#include <cuda_fp16.h>
#include <cstdint>

#define BB 4
#define NN 2048
#define LOG2E 1.4426950408889634f

__device__ float g_Wqkv[64 * 192];
__device__ float g_bqkv[192];
__device__ float g_Wo[64 * 64];
__device__ float g_bo[64];
__device__ float g_fr[2];
__device__ float g_q[BB * NN * 64];       // q rows, pre-scaled by 0.25*log2e
__device__ float g_kt[BB * 64 * NN];      // tf32 K^T [b][h*16+kd][n]
__device__ __half g_vt[BB * 64 * NN];     // f16 V^T [b][h*16+hd][n]
__device__ float g_bf2r[4 * 8 * NN];      // tf32 bf2 [h][c][n]
__device__ float g_ctx[BB * NN * 64];

__device__ __forceinline__ uint32_t f2tf32(float x) {
    uint32_t u; asm("cvt.rna.tf32.f32 %0, %1;" : "=r"(u) : "f"(x)); return u;
}
__device__ __forceinline__ float ex2f(float x) {
    float y; asm("ex2.approx.f32 %0, %1;" : "=f"(y) : "f"(x)); return y;
}
__device__ __forceinline__ uint32_t pack_h2(float lo, float hi) {
    uint32_t r; asm("cvt.rn.f16x2.f32 %0, %1, %2;" : "=r"(r) : "f"(hi), "f"(lo)); return r;
}
#define MMA_TF32(Cr, Ar, Br) asm volatile( \
    "mma.sync.aligned.m16n8k8.row.col.f32.tf32.tf32.f32 " \
    "{%0,%1,%2,%3}, {%4,%5,%6,%7}, {%8,%9}, {%0,%1,%2,%3};" \
    : "+f"(Cr[0]), "+f"(Cr[1]), "+f"(Cr[2]), "+f"(Cr[3]) \
    : "r"(Ar[0]), "r"(Ar[1]), "r"(Ar[2]), "r"(Ar[3]), "r"(Br[0]), "r"(Br[1]))
#define MMA_F16(Dr, Ar, Br) asm volatile( \
    "mma.sync.aligned.m16n8k16.row.col.f32.f16.f16.f32 " \
    "{%0,%1,%2,%3}, {%4,%5,%6,%7}, {%8,%9}, {%0,%1,%2,%3};" \
    : "+f"(Dr[0]), "+f"(Dr[1]), "+f"(Dr[2]), "+f"(Dr[3]) \
    : "r"(Ar[0]), "r"(Ar[1]), "r"(Ar[2]), "r"(Ar[3]), "r"(Br[0]), "r"(Br[1]))
#define CPA(dst, src) asm volatile("cp.async.cg.shared.global [%0], [%1], 16;" :: "r"(dst), "l"(src))
__device__ __forceinline__ float2 lds_v2(uint32_t a) {
    float2 v; asm("ld.shared.v2.f32 {%0,%1}, [%2];" : "=f"(v.x), "=f"(v.y) : "r"(a)); return v;
}
__device__ __forceinline__ uint32_t lds_b32(uint32_t a) {
    uint32_t v; asm("ld.shared.b32 %0, [%1];" : "=r"(v) : "r"(a)); return v;
}

// ---------- kernel 1: fold projections, round bf2 ----------
__global__ void prep_kernel(const float* __restrict__ Wqc, const float* __restrict__ bqc,
                            const float* __restrict__ Wqe, const float* __restrict__ bqe,
                            const float* __restrict__ Woc, const float* __restrict__ boc,
                            const float* __restrict__ Woe, const float* __restrict__ boe,
                            const float* __restrict__ gf, const float* __restrict__ bf2) {
    int gtid = blockIdx.x * 256 + threadIdx.x;
    int gstr = gridDim.x * 256;
    const float QS = 0.25f * LOG2E;
    for (int idx = gtid; idx < 64 * 192; idx += gstr) {
        int i = idx / 192, j = idx % 192;
        float s = 0.f;
#pragma unroll
        for (int c = 0; c < 24; c++) s += Wqc[i * 24 + c] * Wqe[c * 192 + j];
        if (j < 64) s *= QS;
        g_Wqkv[idx] = s;
    }
    for (int j = gtid; j < 192; j += gstr) {
        float s = bqe[j];
#pragma unroll
        for (int c = 0; c < 24; c++) s += bqc[c] * Wqe[c * 192 + j];
        if (j < 64) s *= QS;
        g_bqkv[j] = s;
    }
    for (int idx = gtid; idx < 64 * 64; idx += gstr) {
        int i = idx >> 6, j = idx & 63;
        float s = 0.f;
#pragma unroll
        for (int c = 0; c < 8; c++) s += Woc[i * 8 + c] * Woe[c * 64 + j];
        g_Wo[idx] = s;
    }
    for (int j = gtid; j < 64; j += gstr) {
        float s = boe[j];
#pragma unroll
        for (int c = 0; c < 8; c++) s += boc[c] * Woe[c * 64 + j];
        g_bo[j] = s;
    }
    for (int idx = gtid; idx < 4 * 8 * NN; idx += gstr)
        ((uint32_t*)g_bf2r)[idx] = f2tf32(bf2[idx]);
    if (gtid == 0) {
        float fr = 1.f / (1.f + expf(-gf[0]));
        g_fr[0] = fr * LOG2E;
        g_fr[1] = (1.f - fr) * LOG2E;
    }
}

// ---------- kernel 2: fused QKV projection + K/V transpose ----------
__global__ __launch_bounds__(256) void qkvtr_kernel(const float* __restrict__ feats) {
    __shared__ float sf[32][64];
    __shared__ float4 sW4[64][48];
    __shared__ float sq[32][201];   // kv columns staging (stride 201: transpose-read conflict-free)
    int tid = threadIdx.x;
    int n0g = blockIdx.x * 32;
    for (int idx = tid; idx < 64 * 48; idx += 256)
        sW4[idx / 48][idx % 48] = ((const float4*)g_Wqkv)[idx];
    for (int idx = tid; idx < 32 * 64; idx += 256)
        sf[idx >> 6][idx & 63] = feats[(size_t)n0g * 64 + idx];
    __syncthreads();
    int r = tid >> 3, cg = tid & 7;
    float4 acc[6];
#pragma unroll
    for (int w = 0; w < 6; w++) acc[w] = ((const float4*)g_bqkv)[cg * 6 + w];
#pragma unroll 8
    for (int c = 0; c < 64; c++) {
        float f = sf[r][c];
#pragma unroll
        for (int w = 0; w < 6; w++) {
            float4 wv = sW4[c][cg * 6 + w];
            acc[w].x += f * wv.x; acc[w].y += f * wv.y;
            acc[w].z += f * wv.z; acc[w].w += f * wv.w;
        }
    }
    // direct q writes (cols < 64)
    float* qrow = g_q + (size_t)(n0g + r) * 64 + cg * 24;
    if (cg < 2) {
#pragma unroll
        for (int w = 0; w < 6; w++) *(float4*)(qrow + w * 4) = acc[w];
    } else if (cg == 2) {
#pragma unroll
        for (int w = 0; w < 4; w++) *(float4*)(qrow + w * 4) = acc[w];
    }
    // stage all cols to smem (scalar stores; only cols>=64 used)
#pragma unroll
    for (int w = 0; w < 6; w++) {
        int c0 = cg * 24 + w * 4;
        sq[r][c0 + 0] = acc[w].x; sq[r][c0 + 1] = acc[w].y;
        sq[r][c0 + 2] = acc[w].z; sq[r][c0 + 3] = acc[w].w;
    }
    __syncthreads();
    int b = n0g >> 11, n0 = n0g & (NN - 1);
    int row = tid >> 2;            // 0..63 = h*16 + d
    int rc = (tid & 3) * 8;
    uint32_t* kdst = (uint32_t*)(g_kt + ((size_t)b * 64 + row) * NN + n0 + rc);
    __half* vdst = g_vt + ((size_t)b * 64 + row) * NN + n0 + rc;
#pragma unroll
    for (int i = 0; i < 8; i++) kdst[i] = f2tf32(sq[rc + i][64 + row]);
#pragma unroll
    for (int i = 0; i < 8; i++) vdst[i] = __float2half(sq[rc + i][128 + row]);
}

// ---------- kernel 3: tensor-core fused attention (n-tile 64, 512 threads) ----------
#define BUF_K 0            // 96 rows x 160B  = 15360
#define BUF_V 15360        // 64 rows x 80B   = 5120
#define BUF_L 20480        // 64 rows x 144B  = 9216
#define BUF_F 29696        // 64 rows x 144B  = 9216
#define BUFSZ 38912
#define SMEM_ATTN (2 * BUFSZ + 20480)

__global__ void __launch_bounds__(512, 1) attn_kernel(const float* __restrict__ learned,
                                                      const float* __restrict__ fixedg,
                                                      const float* __restrict__ bf1) {
    extern __shared__ char smem[];
    uint32_t sb = (uint32_t)__cvta_generic_to_shared(smem);
    int tid = threadIdx.x, lane = tid & 31, w = tid >> 5;
    int h = w & 3, p = (w >> 2) & 1, nh = w >> 3;
    int g4 = lane >> 2, t4 = lane & 3;
    int b = blockIdx.x >> 5, n0 = (blockIdx.x & 31) << 6;
    int mo = p << 4;
    int nw = n0 + nh * 32;

    // ---- cp.async plans: 4 x 16B per thread per tile ----
    const char* gsrc0; uint32_t goff0;
    {
        int krow = tid >> 3, sub = tid & 7;
        int hh = krow / 24, kr = krow - hh * 24;
        const float* s = (kr < 16) ? (g_kt + ((size_t)(b * 4 + hh) * 16 + kr) * NN)
                                   : (g_bf2r + ((size_t)(hh * 8 + kr - 16)) * NN);
        gsrc0 = (const char*)(s + sub * 4);
        goff0 = BUF_K + krow * 160 + sub * 16;
    }
    const char* gsrc1; uint32_t goff1; int gstr1;
    if (tid < 256) {
        int krow = 64 + (tid >> 3), sub = tid & 7;
        int hh = krow / 24, kr = krow - hh * 24;
        const float* s = (kr < 16) ? (g_kt + ((size_t)(b * 4 + hh) * 16 + kr) * NN)
                                   : (g_bf2r + ((size_t)(hh * 8 + kr - 16)) * NN);
        gsrc1 = (const char*)(s + sub * 4);
        goff1 = BUF_K + krow * 160 + sub * 16;
        gstr1 = 128;
    } else {
        int v = tid - 256, vrow = v >> 2, sub = v & 3;
        gsrc1 = (const char*)(g_vt + ((size_t)b * 64 + vrow) * NN + sub * 8);
        goff1 = BUF_V + vrow * 80 + sub * 16;
        gstr1 = 64;
    }
    const char* gsrc2; const char* gsrc3; uint32_t goff2, goff3;
    {
        int row = tid >> 3, sub = tid & 7;
        gsrc2 = (const char*)(learned + ((size_t)(b * NN + n0 + row)) * NN + sub * 4);
        goff2 = BUF_L + row * 144 + sub * 16;
        gsrc3 = (const char*)(fixedg + ((size_t)(n0 + row)) * NN + sub * 4);
        goff3 = BUF_F + row * 144 + sub * 16;
    }

    // persistent A fragments: [q*0.25*log2e | bf1*log2e] tf32
    uint32_t Aq[2][3][4];
#pragma unroll
    for (int ns = 0; ns < 2; ns++) {
        int r0 = nw + ns * 16 + g4, r1 = r0 + 8;
#pragma unroll
        for (int ks = 0; ks < 3; ks++) {
            float v0, v1, v2, v3;
            if (ks < 2) {
                const float* q0 = g_q + ((size_t)(b * NN + r0)) * 64 + h * 16 + ks * 8;
                const float* q1 = g_q + ((size_t)(b * NN + r1)) * 64 + h * 16 + ks * 8;
                v0 = q0[t4]; v1 = q1[t4]; v2 = q0[t4 + 4]; v3 = q1[t4 + 4];
            } else {
                const float* f0 = bf1 + ((size_t)(h * NN + r0)) * 8;
                const float* f1 = bf1 + ((size_t)(h * NN + r1)) * 8;
                v0 = f0[t4] * LOG2E; v1 = f1[t4] * LOG2E;
                v2 = f0[t4 + 4] * LOG2E; v3 = f1[t4 + 4] * LOG2E;
            }
            Aq[ns][ks][0] = f2tf32(v0); Aq[ns][ks][1] = f2tf32(v1);
            Aq[ns][ks][2] = f2tf32(v2); Aq[ns][ks][3] = f2tf32(v3);
        }
    }
    float fr2 = g_fr[0], fr12 = g_fr[1];

    float D[2][2][4];
    float lacc[4] = {0.f, 0.f, 0.f, 0.f};
#pragma unroll
    for (int i = 0; i < 16; i++) ((float*)D)[i] = 0.f;

#define ISSUE(T)                                          \
    do {                                                  \
        int t_ = (T);                                     \
        uint32_t bb_ = sb + ((t_ & 1) ? BUFSZ : 0);       \
        CPA(bb_ + goff0, gsrc0 + t_ * 128);               \
        CPA(bb_ + goff1, gsrc1 + t_ * gstr1);             \
        CPA(bb_ + goff2, gsrc2 + t_ * 128);               \
        CPA(bb_ + goff3, gsrc3 + t_ * 128);               \
        asm volatile("cp.async.commit_group;");           \
    } while (0)

    ISSUE(0);
    for (int t = 0; t < 64; t++) {
        if (t < 63) { ISSUE(t + 1); asm volatile("cp.async.wait_group 1;"); }
        else        { asm volatile("cp.async.wait_group 0;"); }
        __syncthreads();
        uint32_t base = sb + ((t & 1) ? BUFSZ : 0);

        // B frags for K|bf2
        uint32_t bk[2][3][2];
        uint32_t kbase = base + BUF_K + h * 24 * 160 + (mo + g4) * 4;
#pragma unroll
        for (int ms = 0; ms < 2; ms++)
#pragma unroll
            for (int ks = 0; ks < 3; ks++) {
                uint32_t a0 = kbase + (ks * 8 + t4) * 160 + ms * 32;
                bk[ms][ks][0] = lds_b32(a0);
                bk[ms][ks][1] = lds_b32(a0 + 640);
            }
        // C init from fused graph
        float C[2][2][4];
        uint32_t gl = base + BUF_L + nh * 32 * 144 + (mo + 2 * t4) * 4;
#pragma unroll
        for (int ns = 0; ns < 2; ns++)
#pragma unroll
            for (int ms = 0; ms < 2; ms++) {
                uint32_t a0 = gl + (ns * 16 + g4) * 144 + ms * 32;
                float2 l0 = lds_v2(a0), l1 = lds_v2(a0 + 8 * 144);
                float2 f0 = lds_v2(a0 + 9216), f1 = lds_v2(a0 + 9216 + 8 * 144);
                C[ns][ms][0] = fmaf(fr2, l0.x, fr12 * f0.x);
                C[ns][ms][1] = fmaf(fr2, l0.y, fr12 * f0.y);
                C[ns][ms][2] = fmaf(fr2, l1.x, fr12 * f1.x);
                C[ns][ms][3] = fmaf(fr2, l1.y, fr12 * f1.y);
            }
#pragma unroll
        for (int ns = 0; ns < 2; ns++)
#pragma unroll
            for (int ms = 0; ms < 2; ms++)
#pragma unroll
                for (int ks = 0; ks < 3; ks++) MMA_TF32(C[ns][ms], Aq[ns][ks], bk[ms][ks]);

        // p = 2^score, row sums
#pragma unroll
        for (int ns = 0; ns < 2; ns++)
#pragma unroll
            for (int ms = 0; ms < 2; ms++) {
                C[ns][ms][0] = ex2f(C[ns][ms][0]);
                C[ns][ms][1] = ex2f(C[ns][ms][1]);
                C[ns][ms][2] = ex2f(C[ns][ms][2]);
                C[ns][ms][3] = ex2f(C[ns][ms][3]);
                lacc[ns * 2 + 0] += C[ns][ms][0] + C[ns][ms][1];
                lacc[ns * 2 + 1] += C[ns][ms][2] + C[ns][ms][3];
            }
        // repack P as f16 A frags
        uint32_t pa[2][4];
#pragma unroll
        for (int ns = 0; ns < 2; ns++) {
            pa[ns][0] = pack_h2(C[ns][0][0], C[ns][0][1]);
            pa[ns][1] = pack_h2(C[ns][0][2], C[ns][0][3]);
            pa[ns][2] = pack_h2(C[ns][1][0], C[ns][1][1]);
            pa[ns][3] = pack_h2(C[ns][1][2], C[ns][1][3]);
        }
        // V B frags + PV mma
        uint32_t bv[2][2];
        uint32_t vb = base + BUF_V + (h * 16 + g4) * 80 + (mo + 2 * t4) * 2;
#pragma unroll
        for (int hs = 0; hs < 2; hs++) {
            bv[hs][0] = lds_b32(vb + hs * 640);
            bv[hs][1] = lds_b32(vb + hs * 640 + 16);
        }
#pragma unroll
        for (int ns = 0; ns < 2; ns++)
#pragma unroll
            for (int hs = 0; hs < 2; hs++) MMA_F16(D[ns][hs], pa[ns], bv[hs]);
        __syncthreads();
    }
#undef ISSUE

    // combine the two m-phase warps
    float* sr = (float*)(smem + 2 * BUFSZ) + ((nh * 4 + h) * 32 + lane) * 20;
    if (p == 1) {
#pragma unroll
        for (int i = 0; i < 16; i++) sr[i] = ((float*)D)[i];
#pragma unroll
        for (int i = 0; i < 4; i++) sr[16 + i] = lacc[i];
    }
    __syncthreads();
    if (p == 0) {
#pragma unroll
        for (int i = 0; i < 16; i++) ((float*)D)[i] += sr[i];
#pragma unroll
        for (int i = 0; i < 4; i++) lacc[i] += sr[16 + i];
        float inv[4];
#pragma unroll
        for (int i = 0; i < 4; i++) {
            float s = lacc[i];
            s += __shfl_xor_sync(0xffffffffu, s, 1);
            s += __shfl_xor_sync(0xffffffffu, s, 2);
            inv[i] = 1.0f / s;
        }
        float* dst = g_ctx + ((size_t)(b * NN + nw)) * 64 + h * 16;
#pragma unroll
        for (int ns = 0; ns < 2; ns++)
#pragma unroll
            for (int rh = 0; rh < 2; rh++) {
                int row = ns * 16 + g4 + rh * 8;
                float iv = inv[ns * 2 + rh];
#pragma unroll
                for (int hs = 0; hs < 2; hs++) {
                    float2 v = make_float2(D[ns][hs][rh * 2] * iv, D[ns][hs][rh * 2 + 1] * iv);
                    *(float2*)(dst + (size_t)row * 64 + hs * 8 + 2 * t4) = v;
                }
            }
    }
}

// ---------- kernel 4: output proj + residual + LayerNorm ----------
__global__ __launch_bounds__(256) void epi_kernel(const float* __restrict__ feats,
                                                  const float* __restrict__ ln_g,
                                                  const float* __restrict__ ln_b,
                                                  float* __restrict__ out, int out_size) {
    __shared__ float4 sWo[64][16];
    __shared__ float sctx[32][64];
    int tid = threadIdx.x;
    int row0 = blockIdx.x * 32;
    for (int idx = tid; idx < 64 * 16; idx += 256)
        sWo[idx >> 4][idx & 15] = ((const float4*)g_Wo)[idx];
    for (int idx = tid; idx < 512; idx += 256)
        ((float4*)sctx)[idx] = ((const float4*)(g_ctx + (size_t)row0 * 64))[idx];
    __syncthreads();
    int r = tid >> 3, cg = tid & 7;
    int row = row0 + r;
    float4 y0 = ((const float4*)g_bo)[cg * 2];
    float4 y1 = ((const float4*)g_bo)[cg * 2 + 1];
#pragma unroll 8
    for (int c = 0; c < 64; c++) {
        float f = sctx[r][c];
        float4 w0 = sWo[c][cg * 2], w1 = sWo[c][cg * 2 + 1];
        y0.x += f * w0.x; y0.y += f * w0.y; y0.z += f * w0.z; y0.w += f * w0.w;
        y1.x += f * w1.x; y1.y += f * w1.y; y1.z += f * w1.z; y1.w += f * w1.w;
    }
    float4 r0 = *(const float4*)(feats + (size_t)row * 64 + cg * 8);
    float4 r1 = *(const float4*)(feats + (size_t)row * 64 + cg * 8 + 4);
    y0.x += r0.x; y0.y += r0.y; y0.z += r0.z; y0.w += r0.w;
    y1.x += r1.x; y1.y += r1.y; y1.z += r1.z; y1.w += r1.w;
    float s1 = y0.x + y0.y + y0.z + y0.w + y1.x + y1.y + y1.z + y1.w;
    float s2 = y0.x * y0.x + y0.y * y0.y + y0.z * y0.z + y0.w * y0.w
             + y1.x * y1.x + y1.y * y1.y + y1.z * y1.z + y1.w * y1.w;
#pragma unroll
    for (int off = 4; off; off >>= 1) {
        s1 += __shfl_xor_sync(0xffffffffu, s1, off);
        s2 += __shfl_xor_sync(0xffffffffu, s2, off);
    }
    float mu = s1 * (1.f / 64.f);
    float var = s2 * (1.f / 64.f) - mu * mu;
    float rs = rsqrtf(var + 1e-5f);
    float4 g0 = *(const float4*)(ln_g + cg * 8), g1 = *(const float4*)(ln_g + cg * 8 + 4);
    float4 b0 = *(const float4*)(ln_b + cg * 8), b1 = *(const float4*)(ln_b + cg * 8 + 4);
    float4 o0, o1;
    o0.x = (y0.x - mu) * rs * g0.x + b0.x; o0.y = (y0.y - mu) * rs * g0.y + b0.y;
    o0.z = (y0.z - mu) * rs * g0.z + b0.z; o0.w = (y0.w - mu) * rs * g0.w + b0.w;
    o1.x = (y1.x - mu) * rs * g1.x + b1.x; o1.y = (y1.y - mu) * rs * g1.y + b1.y;
    o1.z = (y1.z - mu) * rs * g1.z + b1.z; o1.w = (y1.w - mu) * rs * g1.w + b1.w;
    *(float4*)(out + (size_t)row * 64 + cg * 8) = o0;
    *(float4*)(out + (size_t)row * 64 + cg * 8 + 4) = o1;
    if (blockIdx.x == 0 && tid == 0) {
        for (int idx = BB * NN * 64; idx < out_size; idx++)
            out[idx] = 1e-5f / 2048.f;
    }
}

// ---------- launch ----------
extern "C" void kernel_launch(void* const* d_in, const int* in_sizes, int n_in,
                              void* d_out, int out_size) {
    const float* feats   = (const float*)d_in[0];
    const float* fixedg  = (const float*)d_in[1];
    const float* learned = (const float*)d_in[2];
    const float* Wqc = (const float*)d_in[3];
    const float* bqc = (const float*)d_in[4];
    const float* Wqe = (const float*)d_in[5];
    const float* bqe = (const float*)d_in[6];
    const float* Woc = (const float*)d_in[7];
    const float* boc = (const float*)d_in[8];
    const float* Woe = (const float*)d_in[9];
    const float* boe = (const float*)d_in[10];
    const float* bf1 = (const float*)d_in[11];
    const float* bf2 = (const float*)d_in[12];
    const float* gf  = (const float*)d_in[13];
    const float* lng = (const float*)d_in[14];
    const float* lnb = (const float*)d_in[15];
    float* out = (float*)d_out;

    cudaFuncSetAttribute(attn_kernel, cudaFuncAttributeMaxDynamicSharedMemorySize, SMEM_ATTN);
    prep_kernel<<<48, 256>>>(Wqc, bqc, Wqe, bqe, Woc, boc, Woe, boe, gf, bf2);
    qkvtr_kernel<<<BB * NN / 32, 256>>>(feats);
    attn_kernel<<<BB * NN / 64, 512, SMEM_ATTN>>>(learned, fixedg, bf1);
    epi_kernel<<<BB * NN / 32, 256>>>(feats, lng, lnb, out, out_size);
}

// round 6
// speedup vs baseline: 2.0077x; 1.0225x over previous
#include <cuda_runtime.h>
#include <cuda_fp16.h>
#include <cstdint>

#define BB 4
#define NN 2048
#define LOG2E 1.4426950408889634f

__device__ float g_Wqkv[64 * 192];
__device__ float g_bqkv[192];
__device__ float g_Wo[64 * 64];
__device__ float g_bo[64];
__device__ float g_fr[2];
__device__ float g_q[BB * NN * 64];       // q rows, pre-scaled by 0.25*log2e
__device__ float g_kt[BB * 64 * NN];      // tf32 K^T [b][h*16+kd][n]
__device__ __half g_vt[BB * 64 * NN];     // f16 V^T [b][h*16+hd][n]
__device__ float g_bf2r[4 * 8 * NN];      // tf32 bf2 [h][c][n]

__device__ __forceinline__ uint32_t f2tf32(float x) {
    uint32_t u; asm("cvt.rna.tf32.f32 %0, %1;" : "=r"(u) : "f"(x)); return u;
}
__device__ __forceinline__ float ex2f(float x) {
    float y; asm("ex2.approx.f32 %0, %1;" : "=f"(y) : "f"(x)); return y;
}
__device__ __forceinline__ uint32_t pack_h2(float lo, float hi) {
    uint32_t r; asm("cvt.rn.f16x2.f32 %0, %1, %2;" : "=r"(r) : "f"(hi), "f"(lo)); return r;
}
#define MMA_TF32(Cr, Ar, Br) asm volatile( \
    "mma.sync.aligned.m16n8k8.row.col.f32.tf32.tf32.f32 " \
    "{%0,%1,%2,%3}, {%4,%5,%6,%7}, {%8,%9}, {%0,%1,%2,%3};" \
    : "+f"(Cr[0]), "+f"(Cr[1]), "+f"(Cr[2]), "+f"(Cr[3]) \
    : "r"(Ar[0]), "r"(Ar[1]), "r"(Ar[2]), "r"(Ar[3]), "r"(Br[0]), "r"(Br[1]))
#define MMA_F16(Dr, Ar, Br) asm volatile( \
    "mma.sync.aligned.m16n8k16.row.col.f32.f16.f16.f32 " \
    "{%0,%1,%2,%3}, {%4,%5,%6,%7}, {%8,%9}, {%0,%1,%2,%3};" \
    : "+f"(Dr[0]), "+f"(Dr[1]), "+f"(Dr[2]), "+f"(Dr[3]) \
    : "r"(Ar[0]), "r"(Ar[1]), "r"(Ar[2]), "r"(Ar[3]), "r"(Br[0]), "r"(Br[1]))
#define CPA(dst, src) asm volatile("cp.async.cg.shared.global [%0], [%1], 16;" :: "r"(dst), "l"(src))
__device__ __forceinline__ float2 lds_v2(uint32_t a) {
    float2 v; asm("ld.shared.v2.f32 {%0,%1}, [%2];" : "=f"(v.x), "=f"(v.y) : "r"(a)); return v;
}
__device__ __forceinline__ uint32_t lds_b32(uint32_t a) {
    uint32_t v; asm("ld.shared.b32 %0, [%1];" : "=r"(v) : "r"(a)); return v;
}

// ---------- kernel 1: fold projections, round bf2 ----------
__global__ void prep_kernel(const float* __restrict__ Wqc, const float* __restrict__ bqc,
                            const float* __restrict__ Wqe, const float* __restrict__ bqe,
                            const float* __restrict__ Woc, const float* __restrict__ boc,
                            const float* __restrict__ Woe, const float* __restrict__ boe,
                            const float* __restrict__ gf, const float* __restrict__ bf2) {
    int gtid = blockIdx.x * 256 + threadIdx.x;
    int gstr = gridDim.x * 256;
    const float QS = 0.25f * LOG2E;
    for (int idx = gtid; idx < 64 * 192; idx += gstr) {
        int i = idx / 192, j = idx % 192;
        float s = 0.f;
#pragma unroll
        for (int c = 0; c < 24; c++) s += Wqc[i * 24 + c] * Wqe[c * 192 + j];
        if (j < 64) s *= QS;
        g_Wqkv[idx] = s;
    }
    for (int j = gtid; j < 192; j += gstr) {
        float s = bqe[j];
#pragma unroll
        for (int c = 0; c < 24; c++) s += bqc[c] * Wqe[c * 192 + j];
        if (j < 64) s *= QS;
        g_bqkv[j] = s;
    }
    for (int idx = gtid; idx < 64 * 64; idx += gstr) {
        int i = idx >> 6, j = idx & 63;
        float s = 0.f;
#pragma unroll
        for (int c = 0; c < 8; c++) s += Woc[i * 8 + c] * Woe[c * 64 + j];
        g_Wo[idx] = s;
    }
    for (int j = gtid; j < 64; j += gstr) {
        float s = boe[j];
#pragma unroll
        for (int c = 0; c < 8; c++) s += boc[c] * Woe[c * 64 + j];
        g_bo[j] = s;
    }
    for (int idx = gtid; idx < 4 * 8 * NN; idx += gstr)
        ((uint32_t*)g_bf2r)[idx] = f2tf32(bf2[idx]);
    if (gtid == 0) {
        float fr = 1.f / (1.f + expf(-gf[0]));
        g_fr[0] = fr * LOG2E;
        g_fr[1] = (1.f - fr) * LOG2E;
    }
}

// ---------- kernel 2: fused QKV projection + K/V transpose ----------
__global__ __launch_bounds__(256) void qkvtr_kernel(const float* __restrict__ feats) {
    __shared__ float sf[32][64];
    __shared__ float4 sW4[64][48];
    __shared__ float sq[32][201];
    int tid = threadIdx.x;
    int n0g = blockIdx.x * 32;
    for (int idx = tid; idx < 64 * 48; idx += 256)
        sW4[idx / 48][idx % 48] = ((const float4*)g_Wqkv)[idx];
    for (int idx = tid; idx < 32 * 64; idx += 256)
        sf[idx >> 6][idx & 63] = feats[(size_t)n0g * 64 + idx];
    __syncthreads();
    int r = tid >> 3, cg = tid & 7;
    float4 acc[6];
#pragma unroll
    for (int w = 0; w < 6; w++) acc[w] = ((const float4*)g_bqkv)[cg * 6 + w];
#pragma unroll 8
    for (int c = 0; c < 64; c++) {
        float f = sf[r][c];
#pragma unroll
        for (int w = 0; w < 6; w++) {
            float4 wv = sW4[c][cg * 6 + w];
            acc[w].x += f * wv.x; acc[w].y += f * wv.y;
            acc[w].z += f * wv.z; acc[w].w += f * wv.w;
        }
    }
    float* qrow = g_q + (size_t)(n0g + r) * 64 + cg * 24;
    if (cg < 2) {
#pragma unroll
        for (int w = 0; w < 6; w++) *(float4*)(qrow + w * 4) = acc[w];
    } else if (cg == 2) {
#pragma unroll
        for (int w = 0; w < 4; w++) *(float4*)(qrow + w * 4) = acc[w];
    }
#pragma unroll
    for (int w = 0; w < 6; w++) {
        int c0 = cg * 24 + w * 4;
        sq[r][c0 + 0] = acc[w].x; sq[r][c0 + 1] = acc[w].y;
        sq[r][c0 + 2] = acc[w].z; sq[r][c0 + 3] = acc[w].w;
    }
    __syncthreads();
    int b = n0g >> 11, n0 = n0g & (NN - 1);
    int row = tid >> 2;
    int rc = (tid & 3) * 8;
    uint32_t* kdst = (uint32_t*)(g_kt + ((size_t)b * 64 + row) * NN + n0 + rc);
    __half* vdst = g_vt + ((size_t)b * 64 + row) * NN + n0 + rc;
#pragma unroll
    for (int i = 0; i < 8; i++) kdst[i] = f2tf32(sq[rc + i][64 + row]);
#pragma unroll
    for (int i = 0; i < 8; i++) vdst[i] = __float2half(sq[rc + i][128 + row]);
}

// ---------- kernel 3: tensor-core fused attention + epilogue ----------
// 256 threads = 8 warps = 4 heads x 2 m-phases, n-tile 32, grid 256 (2 CTA/SM).
// Triple-buffered cp.async, single __syncthreads per tile.
// Epilogue (Wo GEMM + residual + LayerNorm) fused, overlaying dead buffers.
#define BUF_K 0            // 96 x 160B = 15360
#define BUF_V 15360        // 64 x 80B  = 5120
#define BUF_G 20480        // 2 x 32 x 144B = 9216
#define BUFSZ 29696
#define SMEM_ATTN (3 * BUFSZ)
// epilogue overlay (bytes from smem base):
#define EP_WO   0                    // 16384B: Wo as float4[64][16]
#define EP_CTX  16384                // 32 x 66 floats = 8448B
#define EP_RED  (16384 + 8448)       // 4h x 32lane x 20 floats = 10240B

__global__ void __launch_bounds__(256, 2) attn_kernel(const float* __restrict__ learned,
                                                      const float* __restrict__ fixedg,
                                                      const float* __restrict__ bf1,
                                                      const float* __restrict__ feats,
                                                      const float* __restrict__ ln_g,
                                                      const float* __restrict__ ln_b,
                                                      float* __restrict__ out, int out_size) {
    extern __shared__ char smem[];
    uint32_t sb = (uint32_t)__cvta_generic_to_shared(smem);
    int tid = threadIdx.x, lane = tid & 31, w = tid >> 5;
    int h = w & 3, p = w >> 2;
    int g4 = lane >> 2, t4 = lane & 3;
    int b = blockIdx.x >> 6, n0 = (blockIdx.x & 63) << 5;
    int mo = p << 4;

    // cp.async plans (per-thread, fixed)
    const float* kp[3]; uint32_t koff[3];
#pragma unroll
    for (int i = 0; i < 3; i++) {
        int idx = tid + 256 * i;
        int hk = idx >> 3, sub = idx & 7;
        int hh = hk / 24, kr = hk - hh * 24;
        const float* s = (kr < 16) ? (g_kt + ((size_t)(b * 4 + hh) * 16 + kr) * NN)
                                   : (g_bf2r + ((size_t)(hh * 8 + kr - 16)) * NN);
        kp[i] = s + sub * 4;
        koff[i] = BUF_K + (hh * 24 + kr) * 160 + sub * 16;
    }
    const __half* vp; uint32_t voff;
    {
        int vrh = tid >> 2, sub = tid & 3;
        vp = g_vt + ((size_t)b * 64 + vrh) * NN + sub * 8;
        voff = BUF_V + vrh * 80 + sub * 16;
    }
    const float *lp, *fp; uint32_t loff, foff;
    {
        int r = tid >> 3, sub = tid & 7;
        lp = learned + ((size_t)(b * NN + n0 + r)) * NN + sub * 4;
        fp = fixedg + ((size_t)(n0 + r)) * NN + sub * 4;
        loff = BUF_G + r * 144 + sub * 16;
        foff = BUF_G + 4608 + r * 144 + sub * 16;
    }

    // persistent A fragments: [q*0.25*log2e | bf1*log2e] tf32
    uint32_t Aq[2][3][4];
#pragma unroll
    for (int ns = 0; ns < 2; ns++) {
        int r0 = n0 + ns * 16 + g4, r1 = r0 + 8;
#pragma unroll
        for (int ks = 0; ks < 3; ks++) {
            float v0, v1, v2, v3;
            if (ks < 2) {
                const float* q0 = g_q + ((size_t)(b * NN + r0)) * 64 + h * 16 + ks * 8;
                const float* q1 = g_q + ((size_t)(b * NN + r1)) * 64 + h * 16 + ks * 8;
                v0 = q0[t4]; v1 = q1[t4]; v2 = q0[t4 + 4]; v3 = q1[t4 + 4];
            } else {
                const float* f0 = bf1 + ((size_t)(h * NN + r0)) * 8;
                const float* f1 = bf1 + ((size_t)(h * NN + r1)) * 8;
                v0 = f0[t4] * LOG2E; v1 = f1[t4] * LOG2E;
                v2 = f0[t4 + 4] * LOG2E; v3 = f1[t4 + 4] * LOG2E;
            }
            Aq[ns][ks][0] = f2tf32(v0); Aq[ns][ks][1] = f2tf32(v1);
            Aq[ns][ks][2] = f2tf32(v2); Aq[ns][ks][3] = f2tf32(v3);
        }
    }
    float fr2 = g_fr[0], fr12 = g_fr[1];

    float D[2][2][4];
    float lacc[4] = {0.f, 0.f, 0.f, 0.f};
#pragma unroll
    for (int i = 0; i < 16; i++) ((float*)D)[i] = 0.f;

    uint32_t bufoff[3] = {0u, (uint32_t)BUFSZ, (uint32_t)(2 * BUFSZ)};
#define ISSUE(T, BI)                                      \
    do {                                                  \
        int t_ = (T);                                     \
        uint32_t bb_ = sb + bufoff[BI];                   \
        CPA(bb_ + koff[0], kp[0] + t_ * 32);              \
        CPA(bb_ + koff[1], kp[1] + t_ * 32);              \
        CPA(bb_ + koff[2], kp[2] + t_ * 32);              \
        CPA(bb_ + voff, vp + t_ * 32);                    \
        CPA(bb_ + loff, lp + t_ * 32);                    \
        CPA(bb_ + foff, fp + t_ * 32);                    \
        asm volatile("cp.async.commit_group;");           \
    } while (0)

    ISSUE(0, 0); ISSUE(1, 1);
    int bi = 0;  // buffer index for tile t
    for (int t = 0; t < 64; t++) {
        if (t < 63) asm volatile("cp.async.wait_group 1;");
        else        asm volatile("cp.async.wait_group 0;");
        __syncthreads();
        if (t < 62) { int nbi = bi + 2; if (nbi >= 3) nbi -= 3; ISSUE(t + 2, nbi); }
        uint32_t base = sb + bufoff[bi];
        bi = (bi == 2) ? 0 : bi + 1;

        // B frags for K|bf2
        uint32_t bk[2][3][2];
        uint32_t kbase = base + BUF_K + h * 24 * 160 + (mo + g4) * 4;
#pragma unroll
        for (int ms = 0; ms < 2; ms++)
#pragma unroll
            for (int ks = 0; ks < 3; ks++) {
                uint32_t a0 = kbase + (ks * 8 + t4) * 160 + ms * 32;
                bk[ms][ks][0] = lds_b32(a0);
                bk[ms][ks][1] = lds_b32(a0 + 640);
            }
        // C init from fused graph
        float C[2][2][4];
        uint32_t gl = base + BUF_G + (mo + 2 * t4) * 4;
#pragma unroll
        for (int ns = 0; ns < 2; ns++)
#pragma unroll
            for (int ms = 0; ms < 2; ms++) {
                uint32_t a0 = gl + (ns * 16 + g4) * 144 + ms * 32;
                float2 l0 = lds_v2(a0), l1 = lds_v2(a0 + 8 * 144);
                float2 f0 = lds_v2(a0 + 4608), f1 = lds_v2(a0 + 4608 + 8 * 144);
                C[ns][ms][0] = fmaf(fr2, l0.x, fr12 * f0.x);
                C[ns][ms][1] = fmaf(fr2, l0.y, fr12 * f0.y);
                C[ns][ms][2] = fmaf(fr2, l1.x, fr12 * f1.x);
                C[ns][ms][3] = fmaf(fr2, l1.y, fr12 * f1.y);
            }
#pragma unroll
        for (int ns = 0; ns < 2; ns++)
#pragma unroll
            for (int ms = 0; ms < 2; ms++)
#pragma unroll
                for (int ks = 0; ks < 3; ks++) MMA_TF32(C[ns][ms], Aq[ns][ks], bk[ms][ks]);
        // p = 2^score, row sums
#pragma unroll
        for (int ns = 0; ns < 2; ns++)
#pragma unroll
            for (int ms = 0; ms < 2; ms++) {
                C[ns][ms][0] = ex2f(C[ns][ms][0]);
                C[ns][ms][1] = ex2f(C[ns][ms][1]);
                C[ns][ms][2] = ex2f(C[ns][ms][2]);
                C[ns][ms][3] = ex2f(C[ns][ms][3]);
                lacc[ns * 2 + 0] += C[ns][ms][0] + C[ns][ms][1];
                lacc[ns * 2 + 1] += C[ns][ms][2] + C[ns][ms][3];
            }
        // repack P as f16 A frags
        uint32_t pa[2][4];
#pragma unroll
        for (int ns = 0; ns < 2; ns++) {
            pa[ns][0] = pack_h2(C[ns][0][0], C[ns][0][1]);
            pa[ns][1] = pack_h2(C[ns][0][2], C[ns][0][3]);
            pa[ns][2] = pack_h2(C[ns][1][0], C[ns][1][1]);
            pa[ns][3] = pack_h2(C[ns][1][2], C[ns][1][3]);
        }
        // V B frags + PV mma
        uint32_t bv[2][2];
        uint32_t vb = base + BUF_V + (h * 16 + g4) * 80 + (mo + 2 * t4) * 2;
#pragma unroll
        for (int hs = 0; hs < 2; hs++) {
            bv[hs][0] = lds_b32(vb + hs * 640);
            bv[hs][1] = lds_b32(vb + hs * 640 + 16);
        }
#pragma unroll
        for (int ns = 0; ns < 2; ns++)
#pragma unroll
            for (int hs = 0; hs < 2; hs++) MMA_F16(D[ns][hs], pa[ns], bv[hs]);
    }
#undef ISSUE

    // ---------------- fused epilogue ----------------
    __syncthreads();  // buffers dead; repurpose smem
    // p==1 warps dump partials; everyone helps load Wo
    float* sWo = (float*)smem;                       // float4[64][16]
    float* sctx = (float*)(smem + EP_CTX);           // [32][66]
    float* sred = (float*)(smem + EP_RED);           // [4][32][20]
    if (p == 1) {
        float* sr = sred + (h * 32 + lane) * 20;
#pragma unroll
        for (int i = 0; i < 16; i++) sr[i] = ((float*)D)[i];
#pragma unroll
        for (int i = 0; i < 4; i++) sr[16 + i] = lacc[i];
    }
#pragma unroll
    for (int k = 0; k < 4; k++)
        ((float4*)sWo)[tid + k * 256] = ((const float4*)g_Wo)[tid + k * 256];
    __syncthreads();
    if (p == 0) {
        float* sr = sred + (h * 32 + lane) * 20;
#pragma unroll
        for (int i = 0; i < 16; i++) ((float*)D)[i] += sr[i];
#pragma unroll
        for (int i = 0; i < 4; i++) lacc[i] += sr[16 + i];
        float inv[4];
#pragma unroll
        for (int i = 0; i < 4; i++) {
            float s = lacc[i];
            s += __shfl_xor_sync(0xffffffffu, s, 1);
            s += __shfl_xor_sync(0xffffffffu, s, 2);
            inv[i] = 1.0f / s;
        }
#pragma unroll
        for (int ns = 0; ns < 2; ns++)
#pragma unroll
            for (int rh = 0; rh < 2; rh++) {
                int row = ns * 16 + g4 + rh * 8;
                float iv = inv[ns * 2 + rh];
#pragma unroll
                for (int hs = 0; hs < 2; hs++) {
                    sctx[row * 66 + h * 16 + hs * 8 + 2 * t4] = D[ns][hs][rh * 2] * iv;
                    sctx[row * 66 + h * 16 + hs * 8 + 2 * t4 + 1] = D[ns][hs][rh * 2 + 1] * iv;
                }
            }
    }
    __syncthreads();
    // Wo GEMM + residual + LayerNorm: 8 threads per row, 8 cols each
    {
        int r = tid >> 3, cg = tid & 7;
        size_t grow = (size_t)(b * NN + n0 + r) * 64;
        float4 y0 = ((const float4*)g_bo)[cg * 2];
        float4 y1 = ((const float4*)g_bo)[cg * 2 + 1];
        const float* cr = sctx + r * 66;
#pragma unroll 8
        for (int c = 0; c < 64; c++) {
            float f = cr[c];
            float4 w0 = ((const float4*)sWo)[c * 16 + cg * 2];
            float4 w1 = ((const float4*)sWo)[c * 16 + cg * 2 + 1];
            y0.x += f * w0.x; y0.y += f * w0.y; y0.z += f * w0.z; y0.w += f * w0.w;
            y1.x += f * w1.x; y1.y += f * w1.y; y1.z += f * w1.z; y1.w += f * w1.w;
        }
        float4 r0 = *(const float4*)(feats + grow + cg * 8);
        float4 r1 = *(const float4*)(feats + grow + cg * 8 + 4);
        y0.x += r0.x; y0.y += r0.y; y0.z += r0.z; y0.w += r0.w;
        y1.x += r1.x; y1.y += r1.y; y1.z += r1.z; y1.w += r1.w;
        float s1 = y0.x + y0.y + y0.z + y0.w + y1.x + y1.y + y1.z + y1.w;
        float s2 = y0.x * y0.x + y0.y * y0.y + y0.z * y0.z + y0.w * y0.w
                 + y1.x * y1.x + y1.y * y1.y + y1.z * y1.z + y1.w * y1.w;
#pragma unroll
        for (int off = 4; off; off >>= 1) {
            s1 += __shfl_xor_sync(0xffffffffu, s1, off);
            s2 += __shfl_xor_sync(0xffffffffu, s2, off);
        }
        float mu = s1 * (1.f / 64.f);
        float var = s2 * (1.f / 64.f) - mu * mu;
        float rs = rsqrtf(var + 1e-5f);
        float4 gg0 = *(const float4*)(ln_g + cg * 8), gg1 = *(const float4*)(ln_g + cg * 8 + 4);
        float4 bb0 = *(const float4*)(ln_b + cg * 8), bb1 = *(const float4*)(ln_b + cg * 8 + 4);
        float4 o0, o1;
        o0.x = (y0.x - mu) * rs * gg0.x + bb0.x; o0.y = (y0.y - mu) * rs * gg0.y + bb0.y;
        o0.z = (y0.z - mu) * rs * gg0.z + bb0.z; o0.w = (y0.w - mu) * rs * gg0.w + bb0.w;
        o1.x = (y1.x - mu) * rs * gg1.x + bb1.x; o1.y = (y1.y - mu) * rs * gg1.y + bb1.y;
        o1.z = (y1.z - mu) * rs * gg1.z + bb1.z; o1.w = (y1.w - mu) * rs * gg1.w + bb1.w;
        *(float4*)(out + grow + cg * 8) = o0;
        *(float4*)(out + grow + cg * 8 + 4) = o1;
    }
    // reg_loss = 1e-5 * mean(|softmax|) == 1e-5 / N exactly
    if (blockIdx.x == 0 && tid == 0) {
        for (int idx = BB * NN * 64; idx < out_size; idx++)
            out[idx] = 1e-5f / 2048.f;
    }
}

// ---------- launch ----------
extern "C" void kernel_launch(void* const* d_in, const int* in_sizes, int n_in,
                              void* d_out, int out_size) {
    const float* feats   = (const float*)d_in[0];
    const float* fixedg  = (const float*)d_in[1];
    const float* learned = (const float*)d_in[2];
    const float* Wqc = (const float*)d_in[3];
    const float* bqc = (const float*)d_in[4];
    const float* Wqe = (const float*)d_in[5];
    const float* bqe = (const float*)d_in[6];
    const float* Woc = (const float*)d_in[7];
    const float* boc = (const float*)d_in[8];
    const float* Woe = (const float*)d_in[9];
    const float* boe = (const float*)d_in[10];
    const float* bf1 = (const float*)d_in[11];
    const float* bf2 = (const float*)d_in[12];
    const float* gf  = (const float*)d_in[13];
    const float* lng = (const float*)d_in[14];
    const float* lnb = (const float*)d_in[15];
    float* out = (float*)d_out;

    cudaFuncSetAttribute(attn_kernel, cudaFuncAttributeMaxDynamicSharedMemorySize, SMEM_ATTN);
    prep_kernel<<<48, 256>>>(Wqc, bqc, Wqe, bqe, Woc, boc, Woe, boe, gf, bf2);
    qkvtr_kernel<<<BB * NN / 32, 256>>>(feats);
    attn_kernel<<<BB * NN / 32, 256, SMEM_ATTN>>>(learned, fixedg, bf1, feats, lng, lnb, out, out_size);
}

// round 9
// speedup vs baseline: 2.0100x; 1.0012x over previous
#include <cuda_runtime.h>
#include <cuda_fp16.h>
#include <cstdint>

#define BB 4
#define NN 2048
#define LOG2E 1.4426950408889634f

__device__ float g_Wqkv[64 * 192];
__device__ float g_bqkv[192];
__device__ float g_Wo[64 * 64];
__device__ float g_bo[64];
__device__ float g_fr[2];
__device__ float g_q[BB * NN * 64];       // q rows, pre-scaled by 0.25*log2e
__device__ float g_kt[BB * 64 * NN];      // tf32 K^T [b][h*16+kd][n]
__device__ __half g_vt[BB * 64 * NN];     // f16 V^T [b][h*16+hd][n]
__device__ float g_bf2r[4 * 8 * NN];      // RNA-rounded tf32 bf2 [h][c][n]

__device__ __forceinline__ uint32_t f2tf32(float x) {
    uint32_t u; asm("cvt.rna.tf32.f32 %0, %1;" : "=r"(u) : "f"(x)); return u;
}
__device__ __forceinline__ float ex2f(float x) {
    float y; asm("ex2.approx.f32 %0, %1;" : "=f"(y) : "f"(x)); return y;
}
__device__ __forceinline__ uint32_t pack_h2(float lo, float hi) {
    uint32_t r; asm("cvt.rn.f16x2.f32 %0, %1, %2;" : "=r"(r) : "f"(hi), "f"(lo)); return r;
}
#define MMA_TF32(Cr, Ar, Br) asm volatile( \
    "mma.sync.aligned.m16n8k8.row.col.f32.tf32.tf32.f32 " \
    "{%0,%1,%2,%3}, {%4,%5,%6,%7}, {%8,%9}, {%0,%1,%2,%3};" \
    : "+f"(Cr[0]), "+f"(Cr[1]), "+f"(Cr[2]), "+f"(Cr[3]) \
    : "r"(Ar[0]), "r"(Ar[1]), "r"(Ar[2]), "r"(Ar[3]), "r"(Br[0]), "r"(Br[1]))
#define MMA_F16(Dr, Ar, Br) asm volatile( \
    "mma.sync.aligned.m16n8k16.row.col.f32.f16.f16.f32 " \
    "{%0,%1,%2,%3}, {%4,%5,%6,%7}, {%8,%9}, {%0,%1,%2,%3};" \
    : "+f"(Dr[0]), "+f"(Dr[1]), "+f"(Dr[2]), "+f"(Dr[3]) \
    : "r"(Ar[0]), "r"(Ar[1]), "r"(Ar[2]), "r"(Ar[3]), "r"(Br[0]), "r"(Br[1]))
#define CPA(dst, src) asm volatile("cp.async.cg.shared.global [%0], [%1], 16;" :: "r"(dst), "l"(src))
__device__ __forceinline__ float2 lds_v2(uint32_t a) {
    float2 v; asm("ld.shared.v2.f32 {%0,%1}, [%2];" : "=f"(v.x), "=f"(v.y) : "r"(a)); return v;
}
__device__ __forceinline__ uint32_t lds_b32(uint32_t a) {
    uint32_t v; asm("ld.shared.b32 %0, [%1];" : "=r"(v) : "r"(a)); return v;
}

// ---------- kernel 1: fold low-rank projections + RNA-round bf2 ----------
// grid 66 x 256 = 16896 threads >= 12288 + 4096 + 192 + 64 + 1 = 16641 outputs
__global__ __launch_bounds__(256) void prep_kernel(const float* __restrict__ Wqc, const float* __restrict__ bqc,
                            const float* __restrict__ Wqe, const float* __restrict__ bqe,
                            const float* __restrict__ Woc, const float* __restrict__ boc,
                            const float* __restrict__ Woe, const float* __restrict__ boe,
                            const float* __restrict__ gf, const float* __restrict__ bf2) {
    int gtid = blockIdx.x * 256 + threadIdx.x;
    const float QS = 0.25f * LOG2E;
    // bf2 RNA rounding: 65536 elements = 16384 float4s
    if (gtid < 16384) {
        float4 v = ((const float4*)bf2)[gtid];
        uint4 o;
        o.x = f2tf32(v.x); o.y = f2tf32(v.y); o.z = f2tf32(v.z); o.w = f2tf32(v.w);
        ((uint4*)g_bf2r)[gtid] = o;
    }
    if (gtid < 64 * 192) {
        int i = gtid / 192, j = gtid % 192;
        float s = 0.f;
#pragma unroll
        for (int c = 0; c < 24; c++) s += Wqc[i * 24 + c] * Wqe[c * 192 + j];
        if (j < 64) s *= QS;
        g_Wqkv[gtid] = s;
    } else {
        int r = gtid - 64 * 192;
        if (r < 4096) {  // Wo fold
            int i = r >> 6, j = r & 63;
            float s = 0.f;
#pragma unroll
            for (int c = 0; c < 8; c++) s += Woc[i * 8 + c] * Woe[c * 64 + j];
            g_Wo[r] = s;
        } else if (r < 4096 + 192) {  // bqkv
            int j = r - 4096;
            float s = bqe[j];
#pragma unroll
            for (int c = 0; c < 24; c++) s += bqc[c] * Wqe[c * 192 + j];
            if (j < 64) s *= QS;
            g_bqkv[j] = s;
        } else if (r < 4096 + 192 + 64) {  // bo
            int j = r - 4096 - 192;
            float s = boe[j];
#pragma unroll
            for (int c = 0; c < 8; c++) s += boc[c] * Woe[c * 64 + j];
            g_bo[j] = s;
        } else if (r == 4096 + 192 + 64) {
            float fr = 1.f / (1.f + expf(-gf[0]));
            g_fr[0] = fr * LOG2E;
            g_fr[1] = (1.f - fr) * LOG2E;
        }
    }
}

// ---------- kernel 2: fused QKV projection + K/V transpose ----------
__global__ __launch_bounds__(256) void qkvtr_kernel(const float* __restrict__ feats) {
    __shared__ float sf[32][64];
    __shared__ float4 sW4[64][48];
    __shared__ float sq[32][201];
    int tid = threadIdx.x;
    int n0g = blockIdx.x * 32;
    for (int idx = tid; idx < 64 * 48; idx += 256)
        sW4[idx / 48][idx % 48] = ((const float4*)g_Wqkv)[idx];
    for (int idx = tid; idx < 32 * 64; idx += 256)
        sf[idx >> 6][idx & 63] = feats[(size_t)n0g * 64 + idx];
    __syncthreads();
    int r = tid >> 3, cg = tid & 7;
    float4 acc[6];
#pragma unroll
    for (int w = 0; w < 6; w++) acc[w] = ((const float4*)g_bqkv)[cg * 6 + w];
#pragma unroll 8
    for (int c = 0; c < 64; c++) {
        float f = sf[r][c];
#pragma unroll
        for (int w = 0; w < 6; w++) {
            float4 wv = sW4[c][cg * 6 + w];
            acc[w].x += f * wv.x; acc[w].y += f * wv.y;
            acc[w].z += f * wv.z; acc[w].w += f * wv.w;
        }
    }
    float* qrow = g_q + (size_t)(n0g + r) * 64 + cg * 24;
    if (cg < 2) {
#pragma unroll
        for (int w = 0; w < 6; w++) *(float4*)(qrow + w * 4) = acc[w];
    } else if (cg == 2) {
#pragma unroll
        for (int w = 0; w < 4; w++) *(float4*)(qrow + w * 4) = acc[w];
    }
#pragma unroll
    for (int w = 0; w < 6; w++) {
        int c0 = cg * 24 + w * 4;
        sq[r][c0 + 0] = acc[w].x; sq[r][c0 + 1] = acc[w].y;
        sq[r][c0 + 2] = acc[w].z; sq[r][c0 + 3] = acc[w].w;
    }
    __syncthreads();
    int b = n0g >> 11, n0 = n0g & (NN - 1);
    int row = tid >> 2;
    int rc = (tid & 3) * 8;
    uint32_t* kdst = (uint32_t*)(g_kt + ((size_t)b * 64 + row) * NN + n0 + rc);
    __half* vdst = g_vt + ((size_t)b * 64 + row) * NN + n0 + rc;
#pragma unroll
    for (int i = 0; i < 8; i++) kdst[i] = f2tf32(sq[rc + i][64 + row]);
#pragma unroll
    for (int i = 0; i < 8; i++) vdst[i] = __float2half(sq[rc + i][128 + row]);
}

// ---------- kernel 3: tensor-core fused attention + epilogue ----------
#define BUF_K 0            // 96 x 160B = 15360
#define BUF_V 15360        // 64 x 80B  = 5120
#define BUF_G 20480        // 2 x 32 x 144B = 9216
#define BUFSZ 29696
#define SMEM_ATTN (3 * BUFSZ)
#define EP_CTX  16384
#define EP_RED  (16384 + 8448)

__global__ void __launch_bounds__(256, 2) attn_kernel(const float* __restrict__ learned,
                                                      const float* __restrict__ fixedg,
                                                      const float* __restrict__ bf1,
                                                      const float* __restrict__ feats,
                                                      const float* __restrict__ ln_g,
                                                      const float* __restrict__ ln_b,
                                                      float* __restrict__ out, int out_size) {
    extern __shared__ char smem[];
    uint32_t sb = (uint32_t)__cvta_generic_to_shared(smem);
    int tid = threadIdx.x, lane = tid & 31, w = tid >> 5;
    int h = w & 3, p = w >> 2;
    int g4 = lane >> 2, t4 = lane & 3;
    int b = blockIdx.x >> 6, n0 = (blockIdx.x & 63) << 5;
    int mo = p << 4;

    const float* kp[3]; uint32_t koff[3];
#pragma unroll
    for (int i = 0; i < 3; i++) {
        int idx = tid + 256 * i;
        int hk = idx >> 3, sub = idx & 7;
        int hh = hk / 24, kr = hk - hh * 24;
        const float* s = (kr < 16) ? (g_kt + ((size_t)(b * 4 + hh) * 16 + kr) * NN)
                                   : (g_bf2r + ((size_t)(hh * 8 + kr - 16)) * NN);
        kp[i] = s + sub * 4;
        koff[i] = BUF_K + (hh * 24 + kr) * 160 + sub * 16;
    }
    const __half* vp; uint32_t voff;
    {
        int vrh = tid >> 2, sub = tid & 3;
        vp = g_vt + ((size_t)b * 64 + vrh) * NN + sub * 8;
        voff = BUF_V + vrh * 80 + sub * 16;
    }
    const float *lp, *fp; uint32_t loff, foff;
    {
        int r = tid >> 3, sub = tid & 7;
        lp = learned + ((size_t)(b * NN + n0 + r)) * NN + sub * 4;
        fp = fixedg + ((size_t)(n0 + r)) * NN + sub * 4;
        loff = BUF_G + r * 144 + sub * 16;
        foff = BUF_G + 4608 + r * 144 + sub * 16;
    }

    // persistent A fragments: [q*0.25*log2e | bf1*log2e]
    uint32_t Aq[2][3][4];
#pragma unroll
    for (int ns = 0; ns < 2; ns++) {
        int r0 = n0 + ns * 16 + g4, r1 = r0 + 8;
#pragma unroll
        for (int ks = 0; ks < 3; ks++) {
            float v0, v1, v2, v3;
            if (ks < 2) {
                const float* q0 = g_q + ((size_t)(b * NN + r0)) * 64 + h * 16 + ks * 8;
                const float* q1 = g_q + ((size_t)(b * NN + r1)) * 64 + h * 16 + ks * 8;
                v0 = q0[t4]; v1 = q1[t4]; v2 = q0[t4 + 4]; v3 = q1[t4 + 4];
            } else {
                const float* f0 = bf1 + ((size_t)(h * NN + r0)) * 8;
                const float* f1 = bf1 + ((size_t)(h * NN + r1)) * 8;
                v0 = f0[t4] * LOG2E; v1 = f1[t4] * LOG2E;
                v2 = f0[t4 + 4] * LOG2E; v3 = f1[t4 + 4] * LOG2E;
            }
            Aq[ns][ks][0] = f2tf32(v0); Aq[ns][ks][1] = f2tf32(v1);
            Aq[ns][ks][2] = f2tf32(v2); Aq[ns][ks][3] = f2tf32(v3);
        }
    }
    float fr2 = g_fr[0], fr12 = g_fr[1];

    float D[2][2][4];
    float lacc[4] = {0.f, 0.f, 0.f, 0.f};
#pragma unroll
    for (int i = 0; i < 16; i++) ((float*)D)[i] = 0.f;

    uint32_t bufoff[3] = {0u, (uint32_t)BUFSZ, (uint32_t)(2 * BUFSZ)};
#define ISSUE(T, BI)                                      \
    do {                                                  \
        int t_ = (T);                                     \
        uint32_t bb_ = sb + bufoff[BI];                   \
        CPA(bb_ + koff[0], kp[0] + t_ * 32);              \
        CPA(bb_ + koff[1], kp[1] + t_ * 32);              \
        CPA(bb_ + koff[2], kp[2] + t_ * 32);              \
        CPA(bb_ + voff, vp + t_ * 32);                    \
        CPA(bb_ + loff, lp + t_ * 32);                    \
        CPA(bb_ + foff, fp + t_ * 32);                    \
        asm volatile("cp.async.commit_group;");           \
    } while (0)

    ISSUE(0, 0); ISSUE(1, 1);
    int bi = 0;
    for (int t = 0; t < 64; t++) {
        if (t < 63) asm volatile("cp.async.wait_group 1;");
        else        asm volatile("cp.async.wait_group 0;");
        __syncthreads();
        if (t < 62) { int nbi = bi + 2; if (nbi >= 3) nbi -= 3; ISSUE(t + 2, nbi); }
        uint32_t base = sb + bufoff[bi];
        bi = (bi == 2) ? 0 : bi + 1;

        // V B frags first (independent of the score chain — overlaps QK MMAs)
        uint32_t bv[2][2];
        uint32_t vb = base + BUF_V + (h * 16 + g4) * 80 + (mo + 2 * t4) * 2;
#pragma unroll
        for (int hs = 0; hs < 2; hs++) {
            bv[hs][0] = lds_b32(vb + hs * 640);
            bv[hs][1] = lds_b32(vb + hs * 640 + 16);
        }
        // B frags for K|bf2
        uint32_t bk[2][3][2];
        uint32_t kbase = base + BUF_K + h * 24 * 160 + (mo + g4) * 4;
#pragma unroll
        for (int ms = 0; ms < 2; ms++)
#pragma unroll
            for (int ks = 0; ks < 3; ks++) {
                uint32_t a0 = kbase + (ks * 8 + t4) * 160 + ms * 32;
                bk[ms][ks][0] = lds_b32(a0);
                bk[ms][ks][1] = lds_b32(a0 + 640);
            }
        // C init from fused graph
        float C[2][2][4];
        uint32_t gl = base + BUF_G + (mo + 2 * t4) * 4;
#pragma unroll
        for (int ns = 0; ns < 2; ns++)
#pragma unroll
            for (int ms = 0; ms < 2; ms++) {
                uint32_t a0 = gl + (ns * 16 + g4) * 144 + ms * 32;
                float2 l0 = lds_v2(a0), l1 = lds_v2(a0 + 8 * 144);
                float2 f0 = lds_v2(a0 + 4608), f1 = lds_v2(a0 + 4608 + 8 * 144);
                C[ns][ms][0] = fmaf(fr2, l0.x, fr12 * f0.x);
                C[ns][ms][1] = fmaf(fr2, l0.y, fr12 * f0.y);
                C[ns][ms][2] = fmaf(fr2, l1.x, fr12 * f1.x);
                C[ns][ms][3] = fmaf(fr2, l1.y, fr12 * f1.y);
            }
#pragma unroll
        for (int ns = 0; ns < 2; ns++)
#pragma unroll
            for (int ms = 0; ms < 2; ms++)
#pragma unroll
                for (int ks = 0; ks < 3; ks++) MMA_TF32(C[ns][ms], Aq[ns][ks], bk[ms][ks]);
        // p = 2^score, row sums
#pragma unroll
        for (int ns = 0; ns < 2; ns++)
#pragma unroll
            for (int ms = 0; ms < 2; ms++) {
                C[ns][ms][0] = ex2f(C[ns][ms][0]);
                C[ns][ms][1] = ex2f(C[ns][ms][1]);
                C[ns][ms][2] = ex2f(C[ns][ms][2]);
                C[ns][ms][3] = ex2f(C[ns][ms][3]);
                lacc[ns * 2 + 0] += C[ns][ms][0] + C[ns][ms][1];
                lacc[ns * 2 + 1] += C[ns][ms][2] + C[ns][ms][3];
            }
        uint32_t pa[2][4];
#pragma unroll
        for (int ns = 0; ns < 2; ns++) {
            pa[ns][0] = pack_h2(C[ns][0][0], C[ns][0][1]);
            pa[ns][1] = pack_h2(C[ns][0][2], C[ns][0][3]);
            pa[ns][2] = pack_h2(C[ns][1][0], C[ns][1][1]);
            pa[ns][3] = pack_h2(C[ns][1][2], C[ns][1][3]);
        }
#pragma unroll
        for (int ns = 0; ns < 2; ns++)
#pragma unroll
            for (int hs = 0; hs < 2; hs++) MMA_F16(D[ns][hs], pa[ns], bv[hs]);
    }
#undef ISSUE

    // ---------------- fused epilogue ----------------
    __syncthreads();
    float* sWo = (float*)smem;
    float* sctx = (float*)(smem + EP_CTX);
    float* sred = (float*)(smem + EP_RED);
    if (p == 1) {
        float* sr = sred + (h * 32 + lane) * 20;
#pragma unroll
        for (int i = 0; i < 16; i++) sr[i] = ((float*)D)[i];
#pragma unroll
        for (int i = 0; i < 4; i++) sr[16 + i] = lacc[i];
    }
#pragma unroll
    for (int k = 0; k < 4; k++)
        ((float4*)sWo)[tid + k * 256] = ((const float4*)g_Wo)[tid + k * 256];
    __syncthreads();
    if (p == 0) {
        float* sr = sred + (h * 32 + lane) * 20;
#pragma unroll
        for (int i = 0; i < 16; i++) ((float*)D)[i] += sr[i];
#pragma unroll
        for (int i = 0; i < 4; i++) lacc[i] += sr[16 + i];
        float inv[4];
#pragma unroll
        for (int i = 0; i < 4; i++) {
            float s = lacc[i];
            s += __shfl_xor_sync(0xffffffffu, s, 1);
            s += __shfl_xor_sync(0xffffffffu, s, 2);
            inv[i] = 1.0f / s;
        }
#pragma unroll
        for (int ns = 0; ns < 2; ns++)
#pragma unroll
            for (int rh = 0; rh < 2; rh++) {
                int row = ns * 16 + g4 + rh * 8;
                float iv = inv[ns * 2 + rh];
#pragma unroll
                for (int hs = 0; hs < 2; hs++) {
                    sctx[row * 66 + h * 16 + hs * 8 + 2 * t4] = D[ns][hs][rh * 2] * iv;
                    sctx[row * 66 + h * 16 + hs * 8 + 2 * t4 + 1] = D[ns][hs][rh * 2 + 1] * iv;
                }
            }
    }
    __syncthreads();
    {
        int r = tid >> 3, cg = tid & 7;
        size_t grow = (size_t)(b * NN + n0 + r) * 64;
        float4 y0 = ((const float4*)g_bo)[cg * 2];
        float4 y1 = ((const float4*)g_bo)[cg * 2 + 1];
        const float* cr = sctx + r * 66;
#pragma unroll 8
        for (int c = 0; c < 64; c++) {
            float f = cr[c];
            float4 w0 = ((const float4*)sWo)[c * 16 + cg * 2];
            float4 w1 = ((const float4*)sWo)[c * 16 + cg * 2 + 1];
            y0.x += f * w0.x; y0.y += f * w0.y; y0.z += f * w0.z; y0.w += f * w0.w;
            y1.x += f * w1.x; y1.y += f * w1.y; y1.z += f * w1.z; y1.w += f * w1.w;
        }
        float4 r0 = *(const float4*)(feats + grow + cg * 8);
        float4 r1 = *(const float4*)(feats + grow + cg * 8 + 4);
        y0.x += r0.x; y0.y += r0.y; y0.z += r0.z; y0.w += r0.w;
        y1.x += r1.x; y1.y += r1.y; y1.z += r1.z; y1.w += r1.w;
        float s1 = y0.x + y0.y + y0.z + y0.w + y1.x + y1.y + y1.z + y1.w;
        float s2 = y0.x * y0.x + y0.y * y0.y + y0.z * y0.z + y0.w * y0.w
                 + y1.x * y1.x + y1.y * y1.y + y1.z * y1.z + y1.w * y1.w;
#pragma unroll
        for (int off = 4; off; off >>= 1) {
            s1 += __shfl_xor_sync(0xffffffffu, s1, off);
            s2 += __shfl_xor_sync(0xffffffffu, s2, off);
        }
        float mu = s1 * (1.f / 64.f);
        float var = s2 * (1.f / 64.f) - mu * mu;
        float rs = rsqrtf(var + 1e-5f);
        float4 gg0 = *(const float4*)(ln_g + cg * 8), gg1 = *(const float4*)(ln_g + cg * 8 + 4);
        float4 bb0 = *(const float4*)(ln_b + cg * 8), bb1 = *(const float4*)(ln_b + cg * 8 + 4);
        float4 o0, o1;
        o0.x = (y0.x - mu) * rs * gg0.x + bb0.x; o0.y = (y0.y - mu) * rs * gg0.y + bb0.y;
        o0.z = (y0.z - mu) * rs * gg0.z + bb0.z; o0.w = (y0.w - mu) * rs * gg0.w + bb0.w;
        o1.x = (y1.x - mu) * rs * gg1.x + bb1.x; o1.y = (y1.y - mu) * rs * gg1.y + bb1.y;
        o1.z = (y1.z - mu) * rs * gg1.z + bb1.z; o1.w = (y1.w - mu) * rs * gg1.w + bb1.w;
        *(float4*)(out + grow + cg * 8) = o0;
        *(float4*)(out + grow + cg * 8 + 4) = o1;
    }
    if (blockIdx.x == 0 && tid == 0) {
        for (int idx = BB * NN * 64; idx < out_size; idx++)
            out[idx] = 1e-5f / 2048.f;
    }
}

// ---------- launch ----------
extern "C" void kernel_launch(void* const* d_in, const int* in_sizes, int n_in,
                              void* d_out, int out_size) {
    const float* feats   = (const float*)d_in[0];
    const float* fixedg  = (const float*)d_in[1];
    const float* learned = (const float*)d_in[2];
    const float* Wqc = (const float*)d_in[3];
    const float* bqc = (const float*)d_in[4];
    const float* Wqe = (const float*)d_in[5];
    const float* bqe = (const float*)d_in[6];
    const float* Woc = (const float*)d_in[7];
    const float* boc = (const float*)d_in[8];
    const float* Woe = (const float*)d_in[9];
    const float* boe = (const float*)d_in[10];
    const float* bf1 = (const float*)d_in[11];
    const float* bf2 = (const float*)d_in[12];
    const float* gf  = (const float*)d_in[13];
    const float* lng = (const float*)d_in[14];
    const float* lnb = (const float*)d_in[15];
    float* out = (float*)d_out;

    cudaFuncSetAttribute(attn_kernel, cudaFuncAttributeMaxDynamicSharedMemorySize, SMEM_ATTN);
    prep_kernel<<<66, 256>>>(Wqc, bqc, Wqe, bqe, Woc, boc, Woe, boe, gf, bf2);
    qkvtr_kernel<<<BB * NN / 32, 256>>>(feats);
    attn_kernel<<<BB * NN / 32, 256, SMEM_ATTN>>>(learned, fixedg, bf1, feats, lng, lnb, out, out_size);
}

// round 11
// speedup vs baseline: 2.4438x; 1.2158x over previous
#include <cuda_runtime.h>
#include <cuda_fp16.h>
#include <cstdint>

#define BB 4
#define NN 2048
#define LOG2E 1.4426950408889634f

__device__ float g_Wqkv[64 * 192];
__device__ float g_bqkv[192];
__device__ float g_Wo[64 * 64];
__device__ float g_bo[64];
__device__ float g_fr[2];
__device__ float g_q[BB * NN * 64];       // q rows, pre-scaled by 0.25*log2e
__device__ float g_kt[BB * 64 * NN];      // tf32 K^T [b][h*16+kd][n]
__device__ __half g_vt[BB * 64 * NN];     // f16 V^T [b][h*16+hd][n]
__device__ float g_bf2r[4 * 8 * NN];      // RNA-rounded tf32 bf2 [h][c][n]

__device__ __forceinline__ uint32_t f2tf32(float x) {
    uint32_t u; asm("cvt.rna.tf32.f32 %0, %1;" : "=r"(u) : "f"(x)); return u;
}
__device__ __forceinline__ float ex2f(float x) {
    float y; asm("ex2.approx.f32 %0, %1;" : "=f"(y) : "f"(x)); return y;
}
__device__ __forceinline__ uint32_t pack_h2(float lo, float hi) {
    uint32_t r; asm("cvt.rn.f16x2.f32 %0, %1, %2;" : "=r"(r) : "f"(hi), "f"(lo)); return r;
}
#define MMA_TF32(Cr, Ar, Br) asm volatile( \
    "mma.sync.aligned.m16n8k8.row.col.f32.tf32.tf32.f32 " \
    "{%0,%1,%2,%3}, {%4,%5,%6,%7}, {%8,%9}, {%0,%1,%2,%3};" \
    : "+f"(Cr[0]), "+f"(Cr[1]), "+f"(Cr[2]), "+f"(Cr[3]) \
    : "r"(Ar[0]), "r"(Ar[1]), "r"(Ar[2]), "r"(Ar[3]), "r"(Br[0]), "r"(Br[1]))
#define MMA_F16(Dr, Ar, Br) asm volatile( \
    "mma.sync.aligned.m16n8k16.row.col.f32.f16.f16.f32 " \
    "{%0,%1,%2,%3}, {%4,%5,%6,%7}, {%8,%9}, {%0,%1,%2,%3};" \
    : "+f"(Dr[0]), "+f"(Dr[1]), "+f"(Dr[2]), "+f"(Dr[3]) \
    : "r"(Ar[0]), "r"(Ar[1]), "r"(Ar[2]), "r"(Ar[3]), "r"(Br[0]), "r"(Br[1]))
#define CPA(dst, src) asm volatile("cp.async.cg.shared.global [%0], [%1], 16;" :: "r"(dst), "l"(src))
__device__ __forceinline__ float2 lds_v2(uint32_t a) {
    float2 v; asm("ld.shared.v2.f32 {%0,%1}, [%2];" : "=f"(v.x), "=f"(v.y) : "r"(a)); return v;
}
__device__ __forceinline__ uint32_t lds_b32(uint32_t a) {
    uint32_t v; asm("ld.shared.b32 %0, [%1];" : "=r"(v) : "r"(a)); return v;
}

// ---------- kernel 1: fold low-rank projections + RNA-round bf2 ----------
// grid 66 x 256 = 16896 threads >= 12288 + 4096 + 192 + 64 + 1 = 16641 outputs
__global__ __launch_bounds__(256) void prep_kernel(const float* __restrict__ Wqc, const float* __restrict__ bqc,
                            const float* __restrict__ Wqe, const float* __restrict__ bqe,
                            const float* __restrict__ Woc, const float* __restrict__ boc,
                            const float* __restrict__ Woe, const float* __restrict__ boe,
                            const float* __restrict__ gf, const float* __restrict__ bf2) {
    int gtid = blockIdx.x * 256 + threadIdx.x;
    const float QS = 0.25f * LOG2E;
    if (gtid < 16384) {
        float4 v = ((const float4*)bf2)[gtid];
        uint4 o;
        o.x = f2tf32(v.x); o.y = f2tf32(v.y); o.z = f2tf32(v.z); o.w = f2tf32(v.w);
        ((uint4*)g_bf2r)[gtid] = o;
    }
    if (gtid < 64 * 192) {
        int i = gtid / 192, j = gtid % 192;
        float s = 0.f;
#pragma unroll
        for (int c = 0; c < 24; c++) s += Wqc[i * 24 + c] * Wqe[c * 192 + j];
        if (j < 64) s *= QS;
        g_Wqkv[gtid] = s;
    } else {
        int r = gtid - 64 * 192;
        if (r < 4096) {
            int i = r >> 6, j = r & 63;
            float s = 0.f;
#pragma unroll
            for (int c = 0; c < 8; c++) s += Woc[i * 8 + c] * Woe[c * 64 + j];
            g_Wo[r] = s;
        } else if (r < 4096 + 192) {
            int j = r - 4096;
            float s = bqe[j];
#pragma unroll
            for (int c = 0; c < 24; c++) s += bqc[c] * Wqe[c * 192 + j];
            if (j < 64) s *= QS;
            g_bqkv[j] = s;
        } else if (r < 4096 + 192 + 64) {
            int j = r - 4096 - 192;
            float s = boe[j];
#pragma unroll
            for (int c = 0; c < 8; c++) s += boc[c] * Woe[c * 64 + j];
            g_bo[j] = s;
        } else if (r == 4096 + 192 + 64) {
            float fr = 1.f / (1.f + expf(-gf[0]));
            g_fr[0] = fr * LOG2E;
            g_fr[1] = (1.f - fr) * LOG2E;
        }
    }
}

// ---------- kernel 2: fused QKV projection + K/V transpose ----------
__global__ __launch_bounds__(256) void qkvtr_kernel(const float* __restrict__ feats) {
    __shared__ float sf[32][64];
    __shared__ float4 sW4[64][48];
    __shared__ float sq[32][201];
    int tid = threadIdx.x;
    int n0g = blockIdx.x * 32;
    for (int idx = tid; idx < 64 * 48; idx += 256)
        sW4[idx / 48][idx % 48] = ((const float4*)g_Wqkv)[idx];
    for (int idx = tid; idx < 32 * 64; idx += 256)
        sf[idx >> 6][idx & 63] = feats[(size_t)n0g * 64 + idx];
    __syncthreads();
    int r = tid >> 3, cg = tid & 7;
    float4 acc[6];
#pragma unroll
    for (int w = 0; w < 6; w++) acc[w] = ((const float4*)g_bqkv)[cg * 6 + w];
#pragma unroll 8
    for (int c = 0; c < 64; c++) {
        float f = sf[r][c];
#pragma unroll
        for (int w = 0; w < 6; w++) {
            float4 wv = sW4[c][cg * 6 + w];
            acc[w].x += f * wv.x; acc[w].y += f * wv.y;
            acc[w].z += f * wv.z; acc[w].w += f * wv.w;
        }
    }
    float* qrow = g_q + (size_t)(n0g + r) * 64 + cg * 24;
    if (cg < 2) {
#pragma unroll
        for (int w = 0; w < 6; w++) *(float4*)(qrow + w * 4) = acc[w];
    } else if (cg == 2) {
#pragma unroll
        for (int w = 0; w < 4; w++) *(float4*)(qrow + w * 4) = acc[w];
    }
#pragma unroll
    for (int w = 0; w < 6; w++) {
        int c0 = cg * 24 + w * 4;
        sq[r][c0 + 0] = acc[w].x; sq[r][c0 + 1] = acc[w].y;
        sq[r][c0 + 2] = acc[w].z; sq[r][c0 + 3] = acc[w].w;
    }
    __syncthreads();
    int b = n0g >> 11, n0 = n0g & (NN - 1);
    int row = tid >> 2;
    int rc = (tid & 3) * 8;
    uint32_t* kdst = (uint32_t*)(g_kt + ((size_t)b * 64 + row) * NN + n0 + rc);
    __half* vdst = g_vt + ((size_t)b * 64 + row) * NN + n0 + rc;
#pragma unroll
    for (int i = 0; i < 8; i++) kdst[i] = f2tf32(sq[rc + i][64 + row]);
#pragma unroll
    for (int i = 0; i < 8; i++) vdst[i] = __float2half(sq[rc + i][128 + row]);
}

// ---------- kernel 3: tensor-core fused attention (m-tile 64) + epilogue ----------
// Layout per buffer (double-buffered):
//   K|bf2 : 96 rows x 288B (256B data + 32 pad)        [0, 27648)
//   V     : 64 rows x 144B (128B data + 16 pad)        [27648, 36864)
//   learned: 32 rows x 288B                            [36864, 46080)
//   fixed  : 32 rows x 288B                            [46080, 55296)
#define BUF_K 0
#define BUF_V 27648
#define BUF_L 36864
#define BUF_F 46080
#define BUFSZ 55296
#define SMEM_ATTN (2 * BUFSZ)
#define EP_CTX  16384
#define EP_RED  (16384 + 8448)

__global__ void __launch_bounds__(256, 2) attn_kernel(const float* __restrict__ learned,
                                                      const float* __restrict__ fixedg,
                                                      const float* __restrict__ bf1,
                                                      const float* __restrict__ feats,
                                                      const float* __restrict__ ln_g,
                                                      const float* __restrict__ ln_b,
                                                      float* __restrict__ out, int out_size) {
    extern __shared__ char smem[];
    uint32_t sb = (uint32_t)__cvta_generic_to_shared(smem);
    int tid = threadIdx.x, lane = tid & 31, w = tid >> 5;
    int h = w & 3, p = w >> 2;
    int g4 = lane >> 2, t4 = lane & 3;
    int b = blockIdx.x >> 6, n0 = (blockIdx.x & 63) << 5;
    int mo = p << 4;

    // ---- cp.async plans: 12 x 16B per thread per 64-m iteration ----
    const float* kp[6];
    {
        int seg = tid & 15, row0 = tid >> 4;
#pragma unroll
        for (int i = 0; i < 6; i++) {
            int row = row0 + 16 * i;
            int hh = row / 24, kr = row - hh * 24;
            const float* s = (kr < 16) ? (g_kt + ((size_t)(b * 4 + hh) * 16 + kr) * NN)
                                       : (g_bf2r + ((size_t)(hh * 8 + kr - 16)) * NN);
            kp[i] = s + seg * 4;
        }
    }
    uint32_t koff0 = BUF_K + (tid >> 4) * 288 + (tid & 15) * 16;
    const __half* vp = g_vt + ((size_t)b * 64 + (tid >> 3)) * NN + (tid & 7) * 8;
    uint32_t voff0 = BUF_V + (tid >> 3) * 144 + (tid & 7) * 16;
    const float* lp = learned + ((size_t)(b * NN + n0 + (tid >> 4))) * NN + (tid & 15) * 4;
    uint32_t loff0 = BUF_L + (tid >> 4) * 288 + (tid & 15) * 16;
    const float* fp = fixedg + ((size_t)(n0 + (tid >> 4))) * NN + (tid & 15) * 4;
    uint32_t foff0 = BUF_F + (tid >> 4) * 288 + (tid & 15) * 16;

    // persistent A fragments: [q*0.25*log2e | bf1*log2e]
    uint32_t Aq[2][3][4];
#pragma unroll
    for (int ns = 0; ns < 2; ns++) {
        int r0 = n0 + ns * 16 + g4, r1 = r0 + 8;
#pragma unroll
        for (int ks = 0; ks < 3; ks++) {
            float v0, v1, v2, v3;
            if (ks < 2) {
                const float* q0 = g_q + ((size_t)(b * NN + r0)) * 64 + h * 16 + ks * 8;
                const float* q1 = g_q + ((size_t)(b * NN + r1)) * 64 + h * 16 + ks * 8;
                v0 = q0[t4]; v1 = q1[t4]; v2 = q0[t4 + 4]; v3 = q1[t4 + 4];
            } else {
                const float* f0 = bf1 + ((size_t)(h * NN + r0)) * 8;
                const float* f1 = bf1 + ((size_t)(h * NN + r1)) * 8;
                v0 = f0[t4] * LOG2E; v1 = f1[t4] * LOG2E;
                v2 = f0[t4 + 4] * LOG2E; v3 = f1[t4 + 4] * LOG2E;
            }
            Aq[ns][ks][0] = f2tf32(v0); Aq[ns][ks][1] = f2tf32(v1);
            Aq[ns][ks][2] = f2tf32(v2); Aq[ns][ks][3] = f2tf32(v3);
        }
    }
    float fr2 = g_fr[0], fr12 = g_fr[1];

    float D[2][2][4];
    float lacc[4] = {0.f, 0.f, 0.f, 0.f};
#pragma unroll
    for (int i = 0; i < 16; i++) ((float*)D)[i] = 0.f;

#define ISSUE(T)                                                     \
    do {                                                             \
        int toff_ = (T) * 64;                                        \
        uint32_t bb_ = sb + (((T) & 1) ? BUFSZ : 0);                 \
        CPA(bb_ + koff0 + 0 * 4608, kp[0] + toff_);                  \
        CPA(bb_ + koff0 + 1 * 4608, kp[1] + toff_);                  \
        CPA(bb_ + koff0 + 2 * 4608, kp[2] + toff_);                  \
        CPA(bb_ + koff0 + 3 * 4608, kp[3] + toff_);                  \
        CPA(bb_ + koff0 + 4 * 4608, kp[4] + toff_);                  \
        CPA(bb_ + koff0 + 5 * 4608, kp[5] + toff_);                  \
        CPA(bb_ + voff0, vp + toff_);                                \
        CPA(bb_ + voff0 + 4608, vp + 32 * NN + toff_);               \
        CPA(bb_ + loff0, lp + toff_);                                \
        CPA(bb_ + loff0 + 4608, lp + (size_t)16 * NN + toff_);       \
        CPA(bb_ + foff0, fp + toff_);                                \
        CPA(bb_ + foff0 + 4608, fp + (size_t)16 * NN + toff_);       \
        asm volatile("cp.async.commit_group;");                      \
    } while (0)

    ISSUE(0);
    for (int j = 0; j < 32; j++) {
        asm volatile("cp.async.wait_group 0;");
        __syncthreads();
        if (j < 31) ISSUE(j + 1);
        uint32_t base = sb + ((j & 1) ? BUFSZ : 0);

#pragma unroll
        for (int msub = 0; msub < 2; msub++) {
            uint32_t mb = base + msub * 128;    // K / graph: 32 m = 128 bytes (f32)
            uint32_t mbv = base + msub * 64;    // V: 32 m = 64 bytes (f16)
            // V B frags (independent of the score chain)
            uint32_t bv[2][2];
            uint32_t vb = mbv + BUF_V + (h * 16 + g4) * 144 + (mo + 2 * t4) * 2;
#pragma unroll
            for (int hs = 0; hs < 2; hs++) {
                bv[hs][0] = lds_b32(vb + hs * 1152);
                bv[hs][1] = lds_b32(vb + hs * 1152 + 16);
            }
            // K|bf2 B frags
            uint32_t bk[2][3][2];
            uint32_t kbase = mb + BUF_K + h * 24 * 288 + (mo + g4) * 4;
#pragma unroll
            for (int ms = 0; ms < 2; ms++)
#pragma unroll
                for (int ks = 0; ks < 3; ks++) {
                    uint32_t a0 = kbase + (ks * 8 + t4) * 288 + ms * 32;
                    bk[ms][ks][0] = lds_b32(a0);
                    bk[ms][ks][1] = lds_b32(a0 + 1152);
                }
            // C init from fused graph
            float C[2][2][4];
            uint32_t gl = mb + BUF_L + (mo + 2 * t4) * 4;
#pragma unroll
            for (int ns = 0; ns < 2; ns++)
#pragma unroll
                for (int ms = 0; ms < 2; ms++) {
                    uint32_t a0 = gl + (ns * 16 + g4) * 288 + ms * 32;
                    float2 l0 = lds_v2(a0), l1 = lds_v2(a0 + 2304);
                    float2 f0 = lds_v2(a0 + 9216), f1 = lds_v2(a0 + 9216 + 2304);
                    C[ns][ms][0] = fmaf(fr2, l0.x, fr12 * f0.x);
                    C[ns][ms][1] = fmaf(fr2, l0.y, fr12 * f0.y);
                    C[ns][ms][2] = fmaf(fr2, l1.x, fr12 * f1.x);
                    C[ns][ms][3] = fmaf(fr2, l1.y, fr12 * f1.y);
                }
#pragma unroll
            for (int ns = 0; ns < 2; ns++)
#pragma unroll
                for (int ms = 0; ms < 2; ms++)
#pragma unroll
                    for (int ks = 0; ks < 3; ks++) MMA_TF32(C[ns][ms], Aq[ns][ks], bk[ms][ks]);
            // p = 2^score, row sums
#pragma unroll
            for (int ns = 0; ns < 2; ns++)
#pragma unroll
                for (int ms = 0; ms < 2; ms++) {
                    C[ns][ms][0] = ex2f(C[ns][ms][0]);
                    C[ns][ms][1] = ex2f(C[ns][ms][1]);
                    C[ns][ms][2] = ex2f(C[ns][ms][2]);
                    C[ns][ms][3] = ex2f(C[ns][ms][3]);
                    lacc[ns * 2 + 0] += C[ns][ms][0] + C[ns][ms][1];
                    lacc[ns * 2 + 1] += C[ns][ms][2] + C[ns][ms][3];
                }
            uint32_t pa[2][4];
#pragma unroll
            for (int ns = 0; ns < 2; ns++) {
                pa[ns][0] = pack_h2(C[ns][0][0], C[ns][0][1]);
                pa[ns][1] = pack_h2(C[ns][0][2], C[ns][0][3]);
                pa[ns][2] = pack_h2(C[ns][1][0], C[ns][1][1]);
                pa[ns][3] = pack_h2(C[ns][1][2], C[ns][1][3]);
            }
#pragma unroll
            for (int ns = 0; ns < 2; ns++)
#pragma unroll
                for (int hs = 0; hs < 2; hs++) MMA_F16(D[ns][hs], pa[ns], bv[hs]);
        }
    }
#undef ISSUE

    // ---------------- fused epilogue ----------------
    __syncthreads();
    float* sWo = (float*)smem;
    float* sctx = (float*)(smem + EP_CTX);
    float* sred = (float*)(smem + EP_RED);
    if (p == 1) {
        float* sr = sred + (h * 32 + lane) * 20;
#pragma unroll
        for (int i = 0; i < 16; i++) sr[i] = ((float*)D)[i];
#pragma unroll
        for (int i = 0; i < 4; i++) sr[16 + i] = lacc[i];
    }
#pragma unroll
    for (int k = 0; k < 4; k++)
        ((float4*)sWo)[tid + k * 256] = ((const float4*)g_Wo)[tid + k * 256];
    __syncthreads();
    if (p == 0) {
        float* sr = sred + (h * 32 + lane) * 20;
#pragma unroll
        for (int i = 0; i < 16; i++) ((float*)D)[i] += sr[i];
#pragma unroll
        for (int i = 0; i < 4; i++) lacc[i] += sr[16 + i];
        float inv[4];
#pragma unroll
        for (int i = 0; i < 4; i++) {
            float s = lacc[i];
            s += __shfl_xor_sync(0xffffffffu, s, 1);
            s += __shfl_xor_sync(0xffffffffu, s, 2);
            inv[i] = 1.0f / s;
        }
#pragma unroll
        for (int ns = 0; ns < 2; ns++)
#pragma unroll
            for (int rh = 0; rh < 2; rh++) {
                int row = ns * 16 + g4 + rh * 8;
                float iv = inv[ns * 2 + rh];
#pragma unroll
                for (int hs = 0; hs < 2; hs++) {
                    sctx[row * 66 + h * 16 + hs * 8 + 2 * t4] = D[ns][hs][rh * 2] * iv;
                    sctx[row * 66 + h * 16 + hs * 8 + 2 * t4 + 1] = D[ns][hs][rh * 2 + 1] * iv;
                }
            }
    }
    __syncthreads();
    {
        int r = tid >> 3, cg = tid & 7;
        size_t grow = (size_t)(b * NN + n0 + r) * 64;
        float4 y0 = ((const float4*)g_bo)[cg * 2];
        float4 y1 = ((const float4*)g_bo)[cg * 2 + 1];
        const float* cr = sctx + r * 66;
#pragma unroll 8
        for (int c = 0; c < 64; c++) {
            float f = cr[c];
            float4 w0 = ((const float4*)sWo)[c * 16 + cg * 2];
            float4 w1 = ((const float4*)sWo)[c * 16 + cg * 2 + 1];
            y0.x += f * w0.x; y0.y += f * w0.y; y0.z += f * w0.z; y0.w += f * w0.w;
            y1.x += f * w1.x; y1.y += f * w1.y; y1.z += f * w1.z; y1.w += f * w1.w;
        }
        float4 r0 = *(const float4*)(feats + grow + cg * 8);
        float4 r1 = *(const float4*)(feats + grow + cg * 8 + 4);
        y0.x += r0.x; y0.y += r0.y; y0.z += r0.z; y0.w += r0.w;
        y1.x += r1.x; y1.y += r1.y; y1.z += r1.z; y1.w += r1.w;
        float s1 = y0.x + y0.y + y0.z + y0.w + y1.x + y1.y + y1.z + y1.w;
        float s2 = y0.x * y0.x + y0.y * y0.y + y0.z * y0.z + y0.w * y0.w
                 + y1.x * y1.x + y1.y * y1.y + y1.z * y1.z + y1.w * y1.w;
#pragma unroll
        for (int off = 4; off; off >>= 1) {
            s1 += __shfl_xor_sync(0xffffffffu, s1, off);
            s2 += __shfl_xor_sync(0xffffffffu, s2, off);
        }
        float mu = s1 * (1.f / 64.f);
        float var = s2 * (1.f / 64.f) - mu * mu;
        float rs = rsqrtf(var + 1e-5f);
        float4 gg0 = *(const float4*)(ln_g + cg * 8), gg1 = *(const float4*)(ln_g + cg * 8 + 4);
        float4 bb0 = *(const float4*)(ln_b + cg * 8), bb1 = *(const float4*)(ln_b + cg * 8 + 4);
        float4 o0, o1;
        o0.x = (y0.x - mu) * rs * gg0.x + bb0.x; o0.y = (y0.y - mu) * rs * gg0.y + bb0.y;
        o0.z = (y0.z - mu) * rs * gg0.z + bb0.z; o0.w = (y0.w - mu) * rs * gg0.w + bb0.w;
        o1.x = (y1.x - mu) * rs * gg1.x + bb1.x; o1.y = (y1.y - mu) * rs * gg1.y + bb1.y;
        o1.z = (y1.z - mu) * rs * gg1.z + bb1.z; o1.w = (y1.w - mu) * rs * gg1.w + bb1.w;
        *(float4*)(out + grow + cg * 8) = o0;
        *(float4*)(out + grow + cg * 8 + 4) = o1;
    }
    if (blockIdx.x == 0 && tid == 0) {
        for (int idx = BB * NN * 64; idx < out_size; idx++)
            out[idx] = 1e-5f / 2048.f;
    }
}

// ---------- launch ----------
extern "C" void kernel_launch(void* const* d_in, const int* in_sizes, int n_in,
                              void* d_out, int out_size) {
    const float* feats   = (const float*)d_in[0];
    const float* fixedg  = (const float*)d_in[1];
    const float* learned = (const float*)d_in[2];
    const float* Wqc = (const float*)d_in[3];
    const float* bqc = (const float*)d_in[4];
    const float* Wqe = (const float*)d_in[5];
    const float* bqe = (const float*)d_in[6];
    const float* Woc = (const float*)d_in[7];
    const float* boc = (const float*)d_in[8];
    const float* Woe = (const float*)d_in[9];
    const float* boe = (const float*)d_in[10];
    const float* bf1 = (const float*)d_in[11];
    const float* bf2 = (const float*)d_in[12];
    const float* gf  = (const float*)d_in[13];
    const float* lng = (const float*)d_in[14];
    const float* lnb = (const float*)d_in[15];
    float* out = (float*)d_out;

    cudaFuncSetAttribute(attn_kernel, cudaFuncAttributeMaxDynamicSharedMemorySize, SMEM_ATTN);
    prep_kernel<<<66, 256>>>(Wqc, bqc, Wqe, bqe, Woc, boc, Woe, boe, gf, bf2);
    qkvtr_kernel<<<BB * NN / 32, 256>>>(feats);
    attn_kernel<<<BB * NN / 32, 256, SMEM_ATTN>>>(learned, fixedg, bf1, feats, lng, lnb, out, out_size);
}

// round 12
// speedup vs baseline: 2.7347x; 1.1190x over previous
#include <cuda_runtime.h>
#include <cuda_fp16.h>
#include <cstdint>

#define BB 4
#define NN 2048
#define LOG2E 1.4426950408889634f

__device__ float g_Wqkv[64 * 192];
__device__ float g_bqkv[192];
__device__ float g_Wo[64 * 64];
__device__ float g_bo[64];
__device__ float g_fr[2];
__device__ float g_q[BB * NN * 64];        // q rows, pre-scaled by 0.25*log2e
__device__ uint32_t g_kth[BB * 32 * NN];   // f16 K^T pair-rows: [b][h*8+r][m] = half2(K[2r],K[2r+1])
__device__ __half g_vt[BB * 64 * NN];      // f16 V^T [b][h*16+hd][m]
__device__ uint32_t g_bf2h[16 * NN];       // f16 bf2 pair-rows: [h*4+cp][m] = half2(bf2[2cp],bf2[2cp+1])

__device__ __forceinline__ float ex2f(float x) {
    float y; asm("ex2.approx.f32 %0, %1;" : "=f"(y) : "f"(x)); return y;
}
__device__ __forceinline__ uint32_t pack_h2(float lo, float hi) {
    uint32_t r; asm("cvt.rn.f16x2.f32 %0, %1, %2;" : "=r"(r) : "f"(hi), "f"(lo)); return r;
}
#define MMA_F16(Dr, Ar, Br) asm volatile( \
    "mma.sync.aligned.m16n8k16.row.col.f32.f16.f16.f32 " \
    "{%0,%1,%2,%3}, {%4,%5,%6,%7}, {%8,%9}, {%0,%1,%2,%3};" \
    : "+f"(Dr[0]), "+f"(Dr[1]), "+f"(Dr[2]), "+f"(Dr[3]) \
    : "r"(Ar[0]), "r"(Ar[1]), "r"(Ar[2]), "r"(Ar[3]), "r"(Br[0]), "r"(Br[1]))
#define MMA_F16K8(Dr, Ar, Br) asm volatile( \
    "mma.sync.aligned.m16n8k8.row.col.f32.f16.f16.f32 " \
    "{%0,%1,%2,%3}, {%4,%5}, {%6}, {%0,%1,%2,%3};" \
    : "+f"(Dr[0]), "+f"(Dr[1]), "+f"(Dr[2]), "+f"(Dr[3]) \
    : "r"(Ar[0]), "r"(Ar[1]), "r"(Br))
#define CPA(dst, src) asm volatile("cp.async.cg.shared.global [%0], [%1], 16;" :: "r"(dst), "l"(src))
__device__ __forceinline__ float2 lds_v2(uint32_t a) {
    float2 v; asm("ld.shared.v2.f32 {%0,%1}, [%2];" : "=f"(v.x), "=f"(v.y) : "r"(a)); return v;
}
__device__ __forceinline__ uint32_t lds_b32(uint32_t a) {
    uint32_t v; asm("ld.shared.b32 %0, [%1];" : "=r"(v) : "r"(a)); return v;
}

// ---------- kernel 1: fold low-rank projections + pack bf2 to f16 pair-rows ----------
// grid 66 x 256 = 16896 threads >= 16641 one-shot outputs; bf2h (32768) via 2-pass stride loop
__global__ __launch_bounds__(256) void prep_kernel(const float* __restrict__ Wqc, const float* __restrict__ bqc,
                            const float* __restrict__ Wqe, const float* __restrict__ bqe,
                            const float* __restrict__ Woc, const float* __restrict__ boc,
                            const float* __restrict__ Woe, const float* __restrict__ boe,
                            const float* __restrict__ gf, const float* __restrict__ bf2) {
    int gtid = blockIdx.x * 256 + threadIdx.x;
    const float QS = 0.25f * LOG2E;
    for (int idx = gtid; idx < 16 * NN; idx += 66 * 256) {
        int pr = idx >> 11, m = idx & 2047;
        int hh = pr >> 2, c2 = (pr & 3) * 2;
        g_bf2h[(size_t)pr * NN + m] = pack_h2(bf2[(size_t)(hh * 8 + c2) * NN + m],
                                              bf2[(size_t)(hh * 8 + c2 + 1) * NN + m]);
    }
    if (gtid < 64 * 192) {
        int i = gtid / 192, j = gtid % 192;
        float s = 0.f;
#pragma unroll
        for (int c = 0; c < 24; c++) s += Wqc[i * 24 + c] * Wqe[c * 192 + j];
        if (j < 64) s *= QS;
        g_Wqkv[gtid] = s;
    } else {
        int r = gtid - 64 * 192;
        if (r < 4096) {
            int i = r >> 6, j = r & 63;
            float s = 0.f;
#pragma unroll
            for (int c = 0; c < 8; c++) s += Woc[i * 8 + c] * Woe[c * 64 + j];
            g_Wo[r] = s;
        } else if (r < 4096 + 192) {
            int j = r - 4096;
            float s = bqe[j];
#pragma unroll
            for (int c = 0; c < 24; c++) s += bqc[c] * Wqe[c * 192 + j];
            if (j < 64) s *= QS;
            g_bqkv[j] = s;
        } else if (r < 4096 + 192 + 64) {
            int j = r - 4096 - 192;
            float s = boe[j];
#pragma unroll
            for (int c = 0; c < 8; c++) s += boc[c] * Woe[c * 64 + j];
            g_bo[j] = s;
        } else if (r == 4096 + 192 + 64) {
            float fr = 1.f / (1.f + expf(-gf[0]));
            g_fr[0] = fr * LOG2E;
            g_fr[1] = (1.f - fr) * LOG2E;
        }
    }
}

// ---------- kernel 2: fused QKV projection + K (f16 pair-row) / V (f16) transpose ----------
__global__ __launch_bounds__(256) void qkvtr_kernel(const float* __restrict__ feats) {
    __shared__ float sf[32][64];
    __shared__ float4 sW4[64][48];
    __shared__ float sq[32][201];
    int tid = threadIdx.x;
    int n0g = blockIdx.x * 32;
    for (int idx = tid; idx < 64 * 48; idx += 256)
        sW4[idx / 48][idx % 48] = ((const float4*)g_Wqkv)[idx];
    for (int idx = tid; idx < 32 * 64; idx += 256)
        sf[idx >> 6][idx & 63] = feats[(size_t)n0g * 64 + idx];
    __syncthreads();
    int r = tid >> 3, cg = tid & 7;
    float4 acc[6];
#pragma unroll
    for (int w = 0; w < 6; w++) acc[w] = ((const float4*)g_bqkv)[cg * 6 + w];
#pragma unroll 8
    for (int c = 0; c < 64; c++) {
        float f = sf[r][c];
#pragma unroll
        for (int w = 0; w < 6; w++) {
            float4 wv = sW4[c][cg * 6 + w];
            acc[w].x += f * wv.x; acc[w].y += f * wv.y;
            acc[w].z += f * wv.z; acc[w].w += f * wv.w;
        }
    }
    float* qrow = g_q + (size_t)(n0g + r) * 64 + cg * 24;
    if (cg < 2) {
#pragma unroll
        for (int w = 0; w < 6; w++) *(float4*)(qrow + w * 4) = acc[w];
    } else if (cg == 2) {
#pragma unroll
        for (int w = 0; w < 4; w++) *(float4*)(qrow + w * 4) = acc[w];
    }
#pragma unroll
    for (int w = 0; w < 6; w++) {
        int c0 = cg * 24 + w * 4;
        sq[r][c0 + 0] = acc[w].x; sq[r][c0 + 1] = acc[w].y;
        sq[r][c0 + 2] = acc[w].z; sq[r][c0 + 3] = acc[w].w;
    }
    __syncthreads();
    int b = n0g >> 11, n0 = n0g & (NN - 1);
    // K pair-rows: pr = h*8 + rr holds half2(K[h*16+2rr], K[h*16+2rr+1]) along m
    {
        int pr = tid >> 3, mseg = (tid & 7) * 4;
        int hh = pr >> 3, rr = pr & 7;
        int col0 = 64 + hh * 16 + 2 * rr;
        uint32_t* kdst = g_kth + ((size_t)b * 32 + pr) * NN + n0 + mseg;
#pragma unroll
        for (int i = 0; i < 4; i++)
            kdst[i] = pack_h2(sq[mseg + i][col0], sq[mseg + i][col0 + 1]);
    }
    // V rows (f16 elements along m)
    {
        int row = tid >> 2;
        int rc = (tid & 3) * 8;
        __half* vdst = g_vt + ((size_t)b * 64 + row) * NN + n0 + rc;
#pragma unroll
        for (int i = 0; i < 8; i++) vdst[i] = __float2half(sq[rc + i][128 + row]);
    }
}

// ---------- kernel 3: f16 tensor-core fused attention (m-tile 64) + epilogue ----------
// Per buffer (double-buffered):
//   K|bf2 : 48 pair-rows x 288B (256B data + 32 pad)   [0, 13824)    (12 rows/head: 8 K + 4 bf2)
//   V     : 64 rows x 144B (128B + 16 pad)             [13824, 23040)
//   learned: 32 rows x 288B                            [23040, 32256)
//   fixed  : 32 rows x 288B                            [32256, 41472)
#define BUF_K 0
#define BUF_V 13824
#define BUF_L 23040
#define BUF_F 32256
#define BUFSZ 41472
#define SMEM_ATTN (2 * BUFSZ)
#define EP_CTX  16384
#define EP_RED  (16384 + 8448)

__global__ void __launch_bounds__(256, 2) attn_kernel(const float* __restrict__ learned,
                                                      const float* __restrict__ fixedg,
                                                      const float* __restrict__ bf1,
                                                      const float* __restrict__ feats,
                                                      const float* __restrict__ ln_g,
                                                      const float* __restrict__ ln_b,
                                                      float* __restrict__ out, int out_size) {
    extern __shared__ char smem[];
    uint32_t sb = (uint32_t)__cvta_generic_to_shared(smem);
    int tid = threadIdx.x, lane = tid & 31, w = tid >> 5;
    int h = w & 3, p = w >> 2;
    int g4 = lane >> 2, t4 = lane & 3;
    int b = blockIdx.x >> 6, n0 = (blockIdx.x & 63) << 5;
    int mo = p << 4;

    // ---- cp.async plans: 9 x 16B per thread per 64-m iteration ----
    // K|bf2: 48 pair-rows x 256B = 768 chunks -> 3 per thread
    const uint32_t* kp[3]; uint32_t koff[3];
#pragma unroll
    for (int c = 0; c < 3; c++) {
        int idx = tid + 256 * c;
        int row = idx >> 4, seg = idx & 15;
        int hh = row / 12, kr = row - hh * 12;
        const uint32_t* s = (kr < 8) ? (g_kth + ((size_t)(b * 32) + hh * 8 + kr) * NN)
                                     : (g_bf2h + ((size_t)(hh * 4 + kr - 8)) * NN);
        kp[c] = s + seg * 4;
        koff[c] = BUF_K + row * 288 + seg * 16;
    }
    const __half* vp = g_vt + ((size_t)b * 64 + (tid >> 3)) * NN + (tid & 7) * 8;
    uint32_t voff0 = BUF_V + (tid >> 3) * 144 + (tid & 7) * 16;
    const float* lp = learned + ((size_t)(b * NN + n0 + (tid >> 4))) * NN + (tid & 15) * 4;
    uint32_t loff0 = BUF_L + (tid >> 4) * 288 + (tid & 15) * 16;
    const float* fp = fixedg + ((size_t)(n0 + (tid >> 4))) * NN + (tid & 15) * 4;
    uint32_t foff0 = BUF_F + (tid >> 4) * 288 + (tid & 15) * 16;

    // persistent f16 A fragments: q (k16) and bf1*log2e (k8)
    uint32_t Aq16[2][4], Aq8[2][2];
#pragma unroll
    for (int ns = 0; ns < 2; ns++) {
        int r0 = n0 + ns * 16 + g4, r1 = r0 + 8;
        const float* q0 = g_q + ((size_t)(b * NN + r0)) * 64 + h * 16;
        const float* q1 = g_q + ((size_t)(b * NN + r1)) * 64 + h * 16;
        Aq16[ns][0] = pack_h2(q0[2 * t4], q0[2 * t4 + 1]);
        Aq16[ns][1] = pack_h2(q1[2 * t4], q1[2 * t4 + 1]);
        Aq16[ns][2] = pack_h2(q0[2 * t4 + 8], q0[2 * t4 + 9]);
        Aq16[ns][3] = pack_h2(q1[2 * t4 + 8], q1[2 * t4 + 9]);
        const float* f0 = bf1 + ((size_t)(h * NN + r0)) * 8;
        const float* f1 = bf1 + ((size_t)(h * NN + r1)) * 8;
        Aq8[ns][0] = pack_h2(f0[2 * t4] * LOG2E, f0[2 * t4 + 1] * LOG2E);
        Aq8[ns][1] = pack_h2(f1[2 * t4] * LOG2E, f1[2 * t4 + 1] * LOG2E);
    }
    float fr2 = g_fr[0], fr12 = g_fr[1];

    float D[2][2][4];
    float lacc[4] = {0.f, 0.f, 0.f, 0.f};
#pragma unroll
    for (int i = 0; i < 16; i++) ((float*)D)[i] = 0.f;

#define ISSUE(T)                                                     \
    do {                                                             \
        int toff_ = (T) * 64;                                        \
        uint32_t bb_ = sb + (((T) & 1) ? BUFSZ : 0);                 \
        CPA(bb_ + koff[0], kp[0] + toff_);                           \
        CPA(bb_ + koff[1], kp[1] + toff_);                           \
        CPA(bb_ + koff[2], kp[2] + toff_);                           \
        CPA(bb_ + voff0, vp + toff_);                                \
        CPA(bb_ + voff0 + 4608, vp + 32 * NN + toff_);               \
        CPA(bb_ + loff0, lp + toff_);                                \
        CPA(bb_ + loff0 + 4608, lp + (size_t)16 * NN + toff_);       \
        CPA(bb_ + foff0, fp + toff_);                                \
        CPA(bb_ + foff0 + 4608, fp + (size_t)16 * NN + toff_);       \
        asm volatile("cp.async.commit_group;");                      \
    } while (0)

    ISSUE(0);
    for (int j = 0; j < 32; j++) {
        asm volatile("cp.async.wait_group 0;");
        __syncthreads();
        if (j < 31) ISSUE(j + 1);
        uint32_t base = sb + ((j & 1) ? BUFSZ : 0);

#pragma unroll
        for (int msub = 0; msub < 2; msub++) {
            uint32_t mb = base + msub * 128;   // K (half2/m = 4B) and graph (f32/m): 32 m = 128B
            uint32_t mbv = base + msub * 64;   // V: 32 m = 64B (f16)
            // V B frags
            uint32_t bv[2][2];
            uint32_t vb = mbv + BUF_V + (h * 16 + g4) * 144 + (mo + 2 * t4) * 2;
#pragma unroll
            for (int hs = 0; hs < 2; hs++) {
                bv[hs][0] = lds_b32(vb + hs * 1152);
                bv[hs][1] = lds_b32(vb + hs * 1152 + 16);
            }
            // K (k16) + bf2 (k8) B frags, pair-row layout
            uint32_t bk16[2][2], bk8[2];
            uint32_t kb = mb + BUF_K + (h * 12 + t4) * 288 + (mo + g4) * 4;
            uint32_t kb8 = mb + BUF_K + (h * 12 + 8 + t4) * 288 + (mo + g4) * 4;
#pragma unroll
            for (int ms = 0; ms < 2; ms++) {
                bk16[ms][0] = lds_b32(kb + ms * 32);
                bk16[ms][1] = lds_b32(kb + ms * 32 + 4 * 288);
                bk8[ms] = lds_b32(kb8 + ms * 32);
            }
            // C init from fused graph (fp32)
            float C[2][2][4];
            uint32_t gl = mb + BUF_L + (mo + 2 * t4) * 4;
#pragma unroll
            for (int ns = 0; ns < 2; ns++)
#pragma unroll
                for (int ms = 0; ms < 2; ms++) {
                    uint32_t a0 = gl + (ns * 16 + g4) * 288 + ms * 32;
                    float2 l0 = lds_v2(a0), l1 = lds_v2(a0 + 2304);
                    float2 f0 = lds_v2(a0 + 9216), f1 = lds_v2(a0 + 9216 + 2304);
                    C[ns][ms][0] = fmaf(fr2, l0.x, fr12 * f0.x);
                    C[ns][ms][1] = fmaf(fr2, l0.y, fr12 * f0.y);
                    C[ns][ms][2] = fmaf(fr2, l1.x, fr12 * f1.x);
                    C[ns][ms][3] = fmaf(fr2, l1.y, fr12 * f1.y);
                }
#pragma unroll
            for (int ns = 0; ns < 2; ns++)
#pragma unroll
                for (int ms = 0; ms < 2; ms++) {
                    MMA_F16(C[ns][ms], Aq16[ns], bk16[ms]);
                    MMA_F16K8(C[ns][ms], Aq8[ns], bk8[ms]);
                }
            // p = 2^score, row sums
#pragma unroll
            for (int ns = 0; ns < 2; ns++)
#pragma unroll
                for (int ms = 0; ms < 2; ms++) {
                    C[ns][ms][0] = ex2f(C[ns][ms][0]);
                    C[ns][ms][1] = ex2f(C[ns][ms][1]);
                    C[ns][ms][2] = ex2f(C[ns][ms][2]);
                    C[ns][ms][3] = ex2f(C[ns][ms][3]);
                    lacc[ns * 2 + 0] += C[ns][ms][0] + C[ns][ms][1];
                    lacc[ns * 2 + 1] += C[ns][ms][2] + C[ns][ms][3];
                }
            uint32_t pa[2][4];
#pragma unroll
            for (int ns = 0; ns < 2; ns++) {
                pa[ns][0] = pack_h2(C[ns][0][0], C[ns][0][1]);
                pa[ns][1] = pack_h2(C[ns][0][2], C[ns][0][3]);
                pa[ns][2] = pack_h2(C[ns][1][0], C[ns][1][1]);
                pa[ns][3] = pack_h2(C[ns][1][2], C[ns][1][3]);
            }
#pragma unroll
            for (int ns = 0; ns < 2; ns++)
#pragma unroll
                for (int hs = 0; hs < 2; hs++) MMA_F16(D[ns][hs], pa[ns], bv[hs]);
        }
    }
#undef ISSUE

    // ---------------- fused epilogue ----------------
    __syncthreads();
    float* sWo = (float*)smem;
    float* sctx = (float*)(smem + EP_CTX);
    float* sred = (float*)(smem + EP_RED);
    if (p == 1) {
        float* sr = sred + (h * 32 + lane) * 20;
#pragma unroll
        for (int i = 0; i < 16; i++) sr[i] = ((float*)D)[i];
#pragma unroll
        for (int i = 0; i < 4; i++) sr[16 + i] = lacc[i];
    }
#pragma unroll
    for (int k = 0; k < 4; k++)
        ((float4*)sWo)[tid + k * 256] = ((const float4*)g_Wo)[tid + k * 256];
    __syncthreads();
    if (p == 0) {
        float* sr = sred + (h * 32 + lane) * 20;
#pragma unroll
        for (int i = 0; i < 16; i++) ((float*)D)[i] += sr[i];
#pragma unroll
        for (int i = 0; i < 4; i++) lacc[i] += sr[16 + i];
        float inv[4];
#pragma unroll
        for (int i = 0; i < 4; i++) {
            float s = lacc[i];
            s += __shfl_xor_sync(0xffffffffu, s, 1);
            s += __shfl_xor_sync(0xffffffffu, s, 2);
            inv[i] = 1.0f / s;
        }
#pragma unroll
        for (int ns = 0; ns < 2; ns++)
#pragma unroll
            for (int rh = 0; rh < 2; rh++) {
                int row = ns * 16 + g4 + rh * 8;
                float iv = inv[ns * 2 + rh];
#pragma unroll
                for (int hs = 0; hs < 2; hs++) {
                    sctx[row * 66 + h * 16 + hs * 8 + 2 * t4] = D[ns][hs][rh * 2] * iv;
                    sctx[row * 66 + h * 16 + hs * 8 + 2 * t4 + 1] = D[ns][hs][rh * 2 + 1] * iv;
                }
            }
    }
    __syncthreads();
    {
        int r = tid >> 3, cg = tid & 7;
        size_t grow = (size_t)(b * NN + n0 + r) * 64;
        float4 y0 = ((const float4*)g_bo)[cg * 2];
        float4 y1 = ((const float4*)g_bo)[cg * 2 + 1];
        const float* cr = sctx + r * 66;
#pragma unroll 8
        for (int c = 0; c < 64; c++) {
            float f = cr[c];
            float4 w0 = ((const float4*)sWo)[c * 16 + cg * 2];
            float4 w1 = ((const float4*)sWo)[c * 16 + cg * 2 + 1];
            y0.x += f * w0.x; y0.y += f * w0.y; y0.z += f * w0.z; y0.w += f * w0.w;
            y1.x += f * w1.x; y1.y += f * w1.y; y1.z += f * w1.z; y1.w += f * w1.w;
        }
        float4 r0 = *(const float4*)(feats + grow + cg * 8);
        float4 r1 = *(const float4*)(feats + grow + cg * 8 + 4);
        y0.x += r0.x; y0.y += r0.y; y0.z += r0.z; y0.w += r0.w;
        y1.x += r1.x; y1.y += r1.y; y1.z += r1.z; y1.w += r1.w;
        float s1 = y0.x + y0.y + y0.z + y0.w + y1.x + y1.y + y1.z + y1.w;
        float s2 = y0.x * y0.x + y0.y * y0.y + y0.z * y0.z + y0.w * y0.w
                 + y1.x * y1.x + y1.y * y1.y + y1.z * y1.z + y1.w * y1.w;
#pragma unroll
        for (int off = 4; off; off >>= 1) {
            s1 += __shfl_xor_sync(0xffffffffu, s1, off);
            s2 += __shfl_xor_sync(0xffffffffu, s2, off);
        }
        float mu = s1 * (1.f / 64.f);
        float var = s2 * (1.f / 64.f) - mu * mu;
        float rs = rsqrtf(var + 1e-5f);
        float4 gg0 = *(const float4*)(ln_g + cg * 8), gg1 = *(const float4*)(ln_g + cg * 8 + 4);
        float4 bb0 = *(const float4*)(ln_b + cg * 8), bb1 = *(const float4*)(ln_b + cg * 8 + 4);
        float4 o0, o1;
        o0.x = (y0.x - mu) * rs * gg0.x + bb0.x; o0.y = (y0.y - mu) * rs * gg0.y + bb0.y;
        o0.z = (y0.z - mu) * rs * gg0.z + bb0.z; o0.w = (y0.w - mu) * rs * gg0.w + bb0.w;
        o1.x = (y1.x - mu) * rs * gg1.x + bb1.x; o1.y = (y1.y - mu) * rs * gg1.y + bb1.y;
        o1.z = (y1.z - mu) * rs * gg1.z + bb1.z; o1.w = (y1.w - mu) * rs * gg1.w + bb1.w;
        *(float4*)(out + grow + cg * 8) = o0;
        *(float4*)(out + grow + cg * 8 + 4) = o1;
    }
    if (blockIdx.x == 0 && tid == 0) {
        for (int idx = BB * NN * 64; idx < out_size; idx++)
            out[idx] = 1e-5f / 2048.f;
    }
}

// ---------- launch ----------
extern "C" void kernel_launch(void* const* d_in, const int* in_sizes, int n_in,
                              void* d_out, int out_size) {
    const float* feats   = (const float*)d_in[0];
    const float* fixedg  = (const float*)d_in[1];
    const float* learned = (const float*)d_in[2];
    const float* Wqc = (const float*)d_in[3];
    const float* bqc = (const float*)d_in[4];
    const float* Wqe = (const float*)d_in[5];
    const float* bqe = (const float*)d_in[6];
    const float* Woc = (const float*)d_in[7];
    const float* boc = (const float*)d_in[8];
    const float* Woe = (const float*)d_in[9];
    const float* boe = (const float*)d_in[10];
    const float* bf1 = (const float*)d_in[11];
    const float* bf2 = (const float*)d_in[12];
    const float* gf  = (const float*)d_in[13];
    const float* lng = (const float*)d_in[14];
    const float* lnb = (const float*)d_in[15];
    float* out = (float*)d_out;

    cudaFuncSetAttribute(attn_kernel, cudaFuncAttributeMaxDynamicSharedMemorySize, SMEM_ATTN);
    prep_kernel<<<66, 256>>>(Wqc, bqc, Wqe, bqe, Woc, boc, Woe, boe, gf, bf2);
    qkvtr_kernel<<<BB * NN / 32, 256>>>(feats);
    attn_kernel<<<BB * NN / 32, 256, SMEM_ATTN>>>(learned, fixedg, bf1, feats, lng, lnb, out, out_size);
}